// round 10
// baseline (speedup 1.0000x reference)
#include <cuda_runtime.h>
#include <cuda_bf16.h>
#include <math.h>
#include <stdint.h>

#define NN 4096
#define NFEAT 256
#define NHID 64
#define NCLASS 40

// ---------------- scratch ----------------
__device__ float g_H0[NN * 64];
__device__ __align__(16) __nv_bfloat16 g_HT_hi[128 * NN];   // [b*64+d][ctx]
__device__ __align__(16) __nv_bfloat16 g_HT_lo[128 * NN];
__device__ float g_part[8 * NN * 128];
__device__ __align__(16) __nv_bfloat16 g_Q_hi[2 * NN * 64];
__device__ __align__(16) __nv_bfloat16 g_Q_lo[2 * NN * 64];
__device__ __align__(16) __nv_bfloat16 g_K_hi[2 * NN * 64];
__device__ __align__(16) __nv_bfloat16 g_K_lo[2 * NN * 64];
__device__ float g_apart[2 * 8 * NN * 64];

// ---------------- helpers ----------------
__device__ __forceinline__ uint32_t smem_u32(const void* p) {
    uint32_t a;
    asm("{ .reg .u64 t; cvta.to.shared.u64 t, %1; cvt.u32.u64 %0, t; }" : "=r"(a) : "l"(p));
    return a;
}
#define CP_ASYNC16(dst, src) \
    asm volatile("cp.async.ca.shared.global [%0], [%1], 16;" :: "r"(dst), "l"(src))
#define CP_COMMIT() asm volatile("cp.async.commit_group;" ::: "memory")
#define CP_WAIT0() asm volatile("cp.async.wait_group 0;" ::: "memory")

__device__ __forceinline__ void ldsm4(uint32_t& r0, uint32_t& r1, uint32_t& r2, uint32_t& r3,
                                      uint32_t addr) {
    asm volatile("ldmatrix.sync.aligned.m8n8.x4.shared.b16 {%0,%1,%2,%3}, [%4];"
                 : "=r"(r0), "=r"(r1), "=r"(r2), "=r"(r3) : "r"(addr));
}
__device__ __forceinline__ void split_bf16(float v, __nv_bfloat16& hi, __nv_bfloat16& lo) {
    hi = __float2bfloat16(v);
    lo = __float2bfloat16(v - __bfloat162float(hi));
}
__device__ __forceinline__ uint32_t pack2(__nv_bfloat16 a, __nv_bfloat16 b) {
    return (uint32_t)__bfloat16_as_ushort(a) | ((uint32_t)__bfloat16_as_ushort(b) << 16);
}
__device__ __forceinline__ void splitp(float2 v, uint32_t& hi, uint32_t& lo) {
    __nv_bfloat16 h0, l0, h1, l1;
    split_bf16(v.x, h0, l0);
    split_bf16(v.y, h1, l1);
    hi = pack2(h0, h1);
    lo = pack2(l0, l1);
}
__device__ __forceinline__ void mma16816(float d[4], const uint32_t a[4], const uint32_t b[2]) {
    asm volatile(
        "mma.sync.aligned.m16n8k16.row.col.f32.bf16.bf16.f32 "
        "{%0,%1,%2,%3}, {%4,%5,%6,%7}, {%8,%9}, {%0,%1,%2,%3};\n"
        : "+f"(d[0]), "+f"(d[1]), "+f"(d[2]), "+f"(d[3])
        : "r"(a[0]), "r"(a[1]), "r"(a[2]), "r"(a[3]), "r"(b[0]), "r"(b[1]));
}

#define STB 144
__device__ __forceinline__ void load_frag8(uint32_t bh[8][2], uint32_t bl[8][2],
                                           uint32_t hiB, uint32_t loB, int kc, int ldro) {
#pragma unroll
    for (int p = 0; p < 4; p++) {
        uint32_t a1 = hiB + (uint32_t)(p * 16) * STB + kc * 32 + ldro;
        ldsm4(bh[2 * p][0], bh[2 * p][1], bh[2 * p + 1][0], bh[2 * p + 1][1], a1);
        uint32_t a2 = loB + (uint32_t)(p * 16) * STB + kc * 32 + ldro;
        ldsm4(bl[2 * p][0], bl[2 * p][1], bl[2 * p + 1][0], bl[2 * p + 1][1], a2);
    }
}

// ---------------- kernel 1: h_i = x @ W1[i] + b1[i], coalesced transposed store ------
__global__ void k_fc1(const float* __restrict__ x, const float* __restrict__ W1,
                      const float* __restrict__ b1) {
    int br = blockIdx.y;
    int row0 = blockIdx.x * 64;
    __shared__ float As[16][65];
    __shared__ float Bs[16][64];
    __shared__ float hs[64][65];
    const float* W = W1 + br * NFEAT * NHID;
    int t = threadIdx.x;
    int ty = t >> 4, tx = t & 15;
    float acc[4][4] = {};
    for (int k0 = 0; k0 < NFEAT; k0 += 16) {
        int r = t >> 2, kk4 = (t & 3) * 4;
        float4 av = *(const float4*)(x + (size_t)(row0 + r) * NFEAT + k0 + kk4);
        As[kk4 + 0][r] = av.x; As[kk4 + 1][r] = av.y;
        As[kk4 + 2][r] = av.z; As[kk4 + 3][r] = av.w;
        int bk = t >> 4, bo = (t & 15) * 4;
        *(float4*)&Bs[bk][bo] = *(const float4*)(W + (size_t)(k0 + bk) * NHID + bo);
        __syncthreads();
#pragma unroll
        for (int kk = 0; kk < 16; kk++) {
            float a[4], b[4];
#pragma unroll
            for (int i = 0; i < 4; i++) a[i] = As[kk][ty * 4 + i];
#pragma unroll
            for (int j = 0; j < 4; j++) b[j] = Bs[kk][tx * 4 + j];
#pragma unroll
            for (int i = 0; i < 4; i++)
#pragma unroll
                for (int j = 0; j < 4; j++) acc[i][j] += a[i] * b[j];
        }
        __syncthreads();
    }
    const float* bias = b1 + br * NHID;
    if (br == 0) {
#pragma unroll
        for (int i = 0; i < 4; i++) {
            int row = row0 + ty * 4 + i;
#pragma unroll
            for (int j = 0; j < 4; j++) {
                int o = tx * 4 + j;
                g_H0[(size_t)row * 64 + o] = acc[i][j] + bias[o];
            }
        }
    } else {
#pragma unroll
        for (int i = 0; i < 4; i++)
#pragma unroll
            for (int j = 0; j < 4; j++)
                hs[tx * 4 + j][ty * 4 + i] = acc[i][j] + bias[tx * 4 + j];
        __syncthreads();
        int o = t >> 2, ch = (t & 3) * 16;
        uint32_t hp[8], lp[8];
#pragma unroll
        for (int k = 0; k < 8; k++)
            splitp(make_float2(hs[o][ch + 2 * k], hs[o][ch + 2 * k + 1]), hp[k], lp[k]);
        size_t base = (size_t)((br - 1) * 64 + o) * NN + row0 + ch;
        *(uint4*)(g_HT_hi + base) = make_uint4(hp[0], hp[1], hp[2], hp[3]);
        *(uint4*)(g_HT_hi + base + 8) = make_uint4(hp[4], hp[5], hp[6], hp[7]);
        *(uint4*)(g_HT_lo + base) = make_uint4(lp[0], lp[1], lp[2], lp[3]);
        *(uint4*)(g_HT_lo + base + 8) = make_uint4(lp[4], lp[5], lp[6], lp[7]);
    }
}

// ---------------- kernel 2: HMMA split-K of adj_att @ [h1|h2], 64-row CTAs, 2/SM ------
// grid (64, 8), 128 thr. Warp w: rows (w&1)*32 (2 m-tiles), cols (w>>1)*64 (8 n-tiles).
// Buffer = [BHI(18432) | BLO(18432) | ADJ 64x68 fp32 (17408)], double-buffered.
#define HT_TILE (128 * STB)
#define HT_ADJ_OFF (2 * HT_TILE)
#define HT_ADJ_ST 68
#define HT_BUF (HT_ADJ_OFF + 64 * HT_ADJ_ST * 4)    /* 54272 */
#define HT_SMEM (2 * HT_BUF)                         /* 108544 */
__device__ __forceinline__ void hatt_prefetch(uint32_t bufb,
                                              const float* __restrict__ adj_att,
                                              int row0, int c0, int t) {
    const __nv_bfloat16* Bh = g_HT_hi;
    const __nv_bfloat16* Bl = g_HT_lo;
#pragma unroll
    for (int i = 0; i < 16; i++) {         // B tiles: 2 x 128 rows x 8 chunks
        int cid = i * 128 + t;
        int half = cid >> 10, rem = cid & 1023;
        int row = rem >> 3, ch = rem & 7;
        const __nv_bfloat16* src = (half == 0 ? Bh : Bl) + (size_t)row * NN + c0 + ch * 8;
        uint32_t dst = bufb + half * HT_TILE + row * STB + ch * 16;
        CP_ASYNC16(dst, src);
    }
#pragma unroll
    for (int i = 0; i < 8; i++) {          // adj fp32: 64 rows x 16 chunks
        int cid = i * 128 + t;
        int row = cid >> 4, ch = cid & 15;
        const float* src = adj_att + (size_t)(row0 + row) * NN + c0 + ch * 4;
        uint32_t dst = bufb + HT_ADJ_OFF + (uint32_t)(row * HT_ADJ_ST + ch * 4) * 4;
        CP_ASYNC16(dst, src);
    }
}
__global__ void __launch_bounds__(128) k_hatt(const float* __restrict__ adj_att) {
    extern __shared__ char smc[];
    uint32_t sb = smem_u32(smc);
    int t = threadIdx.x, w = t >> 5, lane = t & 31;
    int g = lane >> 2, tig = lane & 3;
    int ldro = (((lane >> 4) & 1) * 8 + (lane & 7)) * STB + ((lane >> 3) & 1) * 16;
    int row0 = blockIdx.x * 64, kbase = blockIdx.y * 512;
    int wm = (w & 1) * 32, wn = (w >> 1) * 64;
    float acc[2][8][4] = {};

    hatt_prefetch(sb, adj_att, row0, kbase, t);
    CP_COMMIT();

    for (int sub = 0; sub < 8; sub++) {
        uint32_t bufo = (sub & 1) ? HT_BUF : 0;
        CP_WAIT0();
        __syncthreads();
        if (sub < 7) {
            hatt_prefetch(sb + (bufo ^ HT_BUF), adj_att, row0, kbase + (sub + 1) * 64, t);
            CP_COMMIT();
        }
        const float* ADJ = (const float*)(smc + bufo + HT_ADJ_OFF);
        uint32_t bhiB = sb + bufo + (uint32_t)wn * STB;
        uint32_t bloB = bhiB + HT_TILE;
        uint32_t bh[2][8][2], bl[2][8][2];
        load_frag8(bh[0], bl[0], bhiB, bloB, 0, ldro);
#pragma unroll
        for (int kc = 0; kc < 4; kc++) {
            int cur = kc & 1;
            if (kc < 3) load_frag8(bh[cur ^ 1], bl[cur ^ 1], bhiB, bloB, kc + 1, ldro);
            int kcol = kc * 16 + 2 * tig;
            uint32_t ah[2][4], al[2][4];
#pragma unroll
            for (int mt = 0; mt < 2; mt++) {
                int ar = wm + mt * 16;
                splitp(*(const float2*)(ADJ + (ar + g) * HT_ADJ_ST + kcol), ah[mt][0], al[mt][0]);
                splitp(*(const float2*)(ADJ + (ar + g + 8) * HT_ADJ_ST + kcol), ah[mt][1], al[mt][1]);
                splitp(*(const float2*)(ADJ + (ar + g) * HT_ADJ_ST + kcol + 8), ah[mt][2], al[mt][2]);
                splitp(*(const float2*)(ADJ + (ar + g + 8) * HT_ADJ_ST + kcol + 8), ah[mt][3], al[mt][3]);
            }
#pragma unroll
            for (int nt = 0; nt < 8; nt++)
#pragma unroll
                for (int mt = 0; mt < 2; mt++) mma16816(acc[mt][nt], ah[mt], bh[cur][nt]);
#pragma unroll
            for (int nt = 0; nt < 8; nt++)
#pragma unroll
                for (int mt = 0; mt < 2; mt++) mma16816(acc[mt][nt], ah[mt], bl[cur][nt]);
#pragma unroll
            for (int nt = 0; nt < 8; nt++)
#pragma unroll
                for (int mt = 0; mt < 2; mt++) mma16816(acc[mt][nt], al[mt], bh[cur][nt]);
        }
    }
    float* outp = g_part + (size_t)blockIdx.y * NN * 128;
#pragma unroll
    for (int mt = 0; mt < 2; mt++)
#pragma unroll
        for (int nt = 0; nt < 8; nt++) {
            int r = row0 + wm + mt * 16 + g;
            int c = wn + nt * 8 + 2 * tig;
            *(float2*)(outp + (size_t)r * 128 + c) = make_float2(acc[mt][nt][0], acc[mt][nt][1]);
            *(float2*)(outp + (size_t)(r + 8) * 128 + c) = make_float2(acc[mt][nt][2], acc[mt][nt][3]);
        }
}

// ---------------- kernel 3: reduce partials + Q/K = hatt @ W + b (unchanged) ----------
#define QK_SMEM (64 * 65 * 4 + 128 * 4 + 2 * 64 * 64 * 4)
__global__ void __launch_bounds__(256) k_qk(const float* __restrict__ WQ,
                                            const float* __restrict__ bQ,
                                            const float* __restrict__ WK,
                                            const float* __restrict__ bK) {
    extern __shared__ char smc[];
    float* As = (float*)smc;
    float* biasS = As + 64 * 65;
    float* Ws = biasS + 128;
    int row0 = blockIdx.x * 64;
    int b = blockIdx.y;
    int t = threadIdx.x;
#pragma unroll
    for (int i = 0; i < 4; i++) {
        int idx = i * 1024 + t * 4;
        int m = idx >> 6, k = idx & 63;
        float4 acc = make_float4(0.f, 0.f, 0.f, 0.f);
#pragma unroll
        for (int s = 0; s < 8; s++) {
            float4 v = *(const float4*)(g_part + ((size_t)s * NN + row0 + m) * 128 + b * 64 + k);
            acc.x += v.x; acc.y += v.y; acc.z += v.z; acc.w += v.w;
        }
        float* p = As + m * 65 + k;
        p[0] = acc.x; p[1] = acc.y; p[2] = acc.z; p[3] = acc.w;
    }
#pragma unroll
    for (int i = 0; i < 4; i++) {
        int idx = i * 1024 + t * 4;
        *(float4*)(Ws + idx) = *(const float4*)(WQ + (size_t)b * 4096 + idx);
        *(float4*)(Ws + 4096 + idx) = *(const float4*)(WK + (size_t)b * 4096 + idx);
    }
    if (t < 64) biasS[t] = bQ[b * 64 + t];
    else if (t < 128) biasS[t] = bK[b * 64 + t - 64];
    __syncthreads();

    int h = t >> 7, dg = (t >> 6) & 1, m = t & 63;
    const float* Wf = Ws + h * 4096;
    float acc[32];
#pragma unroll
    for (int o = 0; o < 32; o++) acc[o] = biasS[h * 64 + dg * 32 + o];
    for (int k = 0; k < 64; k++) {
        float a = As[m * 65 + k];
#pragma unroll
        for (int o4 = 0; o4 < 8; o4++) {
            float4 wv = *(const float4*)(Wf + k * 64 + dg * 32 + o4 * 4);
            acc[o4 * 4 + 0] += a * wv.x;
            acc[o4 * 4 + 1] += a * wv.y;
            acc[o4 * 4 + 2] += a * wv.z;
            acc[o4 * 4 + 3] += a * wv.w;
        }
    }
    uint32_t hp[16], lp[16];
#pragma unroll
    for (int o2 = 0; o2 < 16; o2++)
        splitp(make_float2(acc[o2 * 2], acc[o2 * 2 + 1]), hp[o2], lp[o2]);
    size_t base = ((size_t)b * NN + row0 + m) * 64 + dg * 32;
    __nv_bfloat16* dhi = (h == 0) ? g_Q_hi : g_K_hi;
    __nv_bfloat16* dlo = (h == 0) ? g_Q_lo : g_K_lo;
#pragma unroll
    for (int q = 0; q < 4; q++) {
        *(uint4*)(dhi + base + q * 8) = make_uint4(hp[q*4], hp[q*4+1], hp[q*4+2], hp[q*4+3]);
        *(uint4*)(dlo + base + q * 8) = make_uint4(lp[q*4], lp[q*4+1], lp[q*4+2], lp[q*4+3]);
    }
}

// ---------------- kernel 4: HMMA fused attention, 64-row CTAs, 2/SM ----------------
// grid (64 rowblk, 8 chunk, 2 branch), 128 thr. Warp w: rows w*16..+15, all 64 cols.
// Buffer = [KHI|KLO|HHI|HLO (4x9216) | ADJ 64x68 fp32 (17408)], double-buffered.
#define AT_TILE (64 * STB)
#define AT_ADJ_OFF (4 * AT_TILE)          /* 36864 */
#define AT_ADJ_ST 68
#define AT_BUF (AT_ADJ_OFF + 64 * AT_ADJ_ST * 4)    /* 54272 */
#define AT_SMEM (2 * AT_BUF)                          /* 108544 */
__device__ __forceinline__ void attn_prefetch(uint32_t bufb,
    const __nv_bfloat16* __restrict__ Kh, const __nv_bfloat16* __restrict__ Kl,
    const __nv_bfloat16* __restrict__ Hh, const __nv_bfloat16* __restrict__ Hl,
    const float* __restrict__ adjM, int row0, int c0, int t) {
#pragma unroll
    for (int i = 0; i < 16; i++) {         // K/H tiles: 4 x 64 rows x 8 chunks
        int cid = i * 128 + t;
        int tile = cid >> 9, rem = cid & 511;
        int row = rem >> 3, ch = rem & 7;
        const __nv_bfloat16* src;
        if (tile == 0)      src = Kh + (size_t)(c0 + row) * 64 + ch * 8;
        else if (tile == 1) src = Kl + (size_t)(c0 + row) * 64 + ch * 8;
        else if (tile == 2) src = Hh + (size_t)row * NN + c0 + ch * 8;
        else                src = Hl + (size_t)row * NN + c0 + ch * 8;
        uint32_t dst = bufb + tile * AT_TILE + row * STB + ch * 16;
        CP_ASYNC16(dst, src);
    }
#pragma unroll
    for (int i = 0; i < 8; i++) {          // adj fp32: 64 rows x 16 chunks
        int cid = i * 128 + t;
        int row = cid >> 4, ch = cid & 15;
        const float* src = adjM + (size_t)(row0 + row) * NN + c0 + ch * 4;
        uint32_t dst = bufb + AT_ADJ_OFF + (uint32_t)(row * AT_ADJ_ST + ch * 4) * 4;
        CP_ASYNC16(dst, src);
    }
}
__global__ void __launch_bounds__(128) k_attn(const float* __restrict__ adjs) {
    extern __shared__ char smc[];
    uint32_t sb = smem_u32(smc);
    int t = threadIdx.x, w = t >> 5, lane = t & 31;
    int g = lane >> 2, tig = lane & 3;
    int ldro = (((lane >> 4) & 1) * 8 + (lane & 7)) * STB + ((lane >> 3) & 1) * 16;
    int row0 = blockIdx.x * 64;
    int chunk = blockIdx.y;
    int b = blockIdx.z;
    const float* adjM = adjs + (size_t)b * NN * NN;
    const __nv_bfloat16* Qh = g_Q_hi + (size_t)b * NN * 64;
    const __nv_bfloat16* Ql = g_Q_lo + (size_t)b * NN * 64;
    const __nv_bfloat16* Kh = g_K_hi + (size_t)b * NN * 64;
    const __nv_bfloat16* Kl = g_K_lo + (size_t)b * NN * 64;
    const __nv_bfloat16* Hh = g_HT_hi + (size_t)b * 64 * NN;
    const __nv_bfloat16* Hl = g_HT_lo + (size_t)b * 64 * NN;

    attn_prefetch(sb, Kh, Kl, Hh, Hl, adjM, row0, chunk * 512, t);
    CP_COMMIT();

    // persistent Q fragments (rows w*16..+15, k=d 0..63)
    uint32_t qh[4][4], ql[4][4];
    {
        int qr = row0 + w * 16;
#pragma unroll
        for (int kc = 0; kc < 4; kc++) {
            int kcol = kc * 16 + 2 * tig;
            qh[kc][0] = *(const uint32_t*)(Qh + (size_t)(qr + g) * 64 + kcol);
            qh[kc][1] = *(const uint32_t*)(Qh + (size_t)(qr + g + 8) * 64 + kcol);
            qh[kc][2] = *(const uint32_t*)(Qh + (size_t)(qr + g) * 64 + kcol + 8);
            qh[kc][3] = *(const uint32_t*)(Qh + (size_t)(qr + g + 8) * 64 + kcol + 8);
            ql[kc][0] = *(const uint32_t*)(Ql + (size_t)(qr + g) * 64 + kcol);
            ql[kc][1] = *(const uint32_t*)(Ql + (size_t)(qr + g + 8) * 64 + kcol);
            ql[kc][2] = *(const uint32_t*)(Ql + (size_t)(qr + g) * 64 + kcol + 8);
            ql[kc][3] = *(const uint32_t*)(Ql + (size_t)(qr + g + 8) * 64 + kcol + 8);
        }
    }

    float oacc[8][4] = {};
    for (int sub = 0; sub < 8; sub++) {
        uint32_t bufo = (sub & 1) ? AT_BUF : 0;
        CP_WAIT0();
        __syncthreads();
        if (sub < 7) {
            attn_prefetch(sb + (bufo ^ AT_BUF), Kh, Kl, Hh, Hl, adjM,
                          row0, chunk * 512 + (sub + 1) * 64, t);
            CP_COMMIT();
        }
        uint32_t khiB = sb + bufo, kloB = khiB + AT_TILE;
        uint32_t hhiB = kloB + AT_TILE, hloB = hhiB + AT_TILE;
        const float* ADJ = (const float*)(smc + bufo + AT_ADJ_OFF);

        uint32_t bh[2][8][2], bl[2][8][2];

        // ---- S = Q @ K^T, fragments pipelined one kc ahead ----
        float sacc[8][4] = {};
        load_frag8(bh[0], bl[0], khiB, kloB, 0, ldro);
#pragma unroll
        for (int kc = 0; kc < 4; kc++) {
            int cur = kc & 1;
            if (kc < 3) load_frag8(bh[cur ^ 1], bl[cur ^ 1], khiB, kloB, kc + 1, ldro);
#pragma unroll
            for (int nt = 0; nt < 8; nt++) mma16816(sacc[nt], qh[kc], bh[cur][nt]);
#pragma unroll
            for (int nt = 0; nt < 8; nt++) mma16816(sacc[nt], qh[kc], bl[cur][nt]);
#pragma unroll
            for (int nt = 0; nt < 8; nt++) mma16816(sacc[nt], ql[kc], bh[cur][nt]);
        }

        // prefetch O-phase kc=0 fragments; LDS overlaps the repack ALU below
        load_frag8(bh[0], bl[0], hhiB, hloB, 0, ldro);

        // ---- P = S .* adj, repack C-frag -> A-frag ----
        uint32_t phi[4][4], plo[4][4];
        int mr = w * 16;
#pragma unroll
        for (int nt = 0; nt < 8; nt++) {
            int j0 = nt * 8 + 2 * tig;
            float2 a01 = *(const float2*)(ADJ + (mr + g) * AT_ADJ_ST + j0);
            float2 a23 = *(const float2*)(ADJ + (mr + g + 8) * AT_ADJ_ST + j0);
            uint32_t h01, l01, h23, l23;
            splitp(make_float2(sacc[nt][0] * a01.x, sacc[nt][1] * a01.y), h01, l01);
            splitp(make_float2(sacc[nt][2] * a23.x, sacc[nt][3] * a23.y), h23, l23);
            int kc2 = nt >> 1;
            if ((nt & 1) == 0) {
                phi[kc2][0] = h01; phi[kc2][1] = h23;
                plo[kc2][0] = l01; plo[kc2][1] = l23;
            } else {
                phi[kc2][2] = h01; phi[kc2][3] = h23;
                plo[kc2][2] = l01; plo[kc2][3] = l23;
            }
        }

        // ---- O += P @ H, fragments pipelined one kc ahead ----
#pragma unroll
        for (int kc = 0; kc < 4; kc++) {
            int cur = kc & 1;
            if (kc < 3) load_frag8(bh[cur ^ 1], bl[cur ^ 1], hhiB, hloB, kc + 1, ldro);
#pragma unroll
            for (int nt = 0; nt < 8; nt++) mma16816(oacc[nt], phi[kc], bh[cur][nt]);
#pragma unroll
            for (int nt = 0; nt < 8; nt++) mma16816(oacc[nt], phi[kc], bl[cur][nt]);
#pragma unroll
            for (int nt = 0; nt < 8; nt++) mma16816(oacc[nt], plo[kc], bh[cur][nt]);
        }
    }

    float* outp = g_apart + ((size_t)(b * 8 + chunk) * NN + row0) * 64;
#pragma unroll
    for (int nt = 0; nt < 8; nt++) {
        int r = w * 16 + g;
        int c = nt * 8 + 2 * tig;
        *(float2*)(outp + (size_t)r * 64 + c) = make_float2(oacc[nt][0], oacc[nt][1]);
        *(float2*)(outp + (size_t)(r + 8) * 64 + c) = make_float2(oacc[nt][2], oacc[nt][3]);
    }
}

// ---------------- kernel 5: reduce + normalize + mask + relu + fc2 + log_softmax --------
__global__ void k_final(const float* __restrict__ att, const float* __restrict__ W2,
                        const float* __restrict__ b2, float* __restrict__ out) {
    __shared__ float W2s[192 * NCLASS];
    __shared__ float b2s[NCLASS];
    __shared__ float fin[8][192];
    int t = threadIdx.x;
    for (int i = t; i < 192 * NCLASS; i += 256) W2s[i] = W2[i];
    if (t < NCLASS) b2s[t] = b2[t];

    float a0 = att[0], a1 = att[1], a2 = att[2];
    float am = fmaxf(a0, fmaxf(a1, a2));
    float e0 = expf(a0 - am), e1 = expf(a1 - am), e2 = expf(a2 - am);
    float inv = 1.0f / (e0 + e1 + e2);
    float mask[3] = {e0 * inv, e1 * inv, e2 * inv};

    int w = t >> 5, lane = t & 31;
    int n = blockIdx.x * 8 + w;

    float h[3][2];
    h[0][0] = g_H0[(size_t)n * 64 + lane];
    h[0][1] = g_H0[(size_t)n * 64 + 32 + lane];
#pragma unroll
    for (int b = 0; b < 2; b++) {
        float s0 = 0.f, s1 = 0.f;
#pragma unroll
        for (int c = 0; c < 8; c++) {
            const float* p = g_apart + ((size_t)(b * 8 + c) * NN + n) * 64;
            s0 += p[lane];
            s1 += p[32 + lane];
        }
        h[1 + b][0] = s0;
        h[1 + b][1] = s1;
    }
    __syncthreads();

#pragma unroll
    for (int br = 0; br < 3; br++) {
        float ss = h[br][0] * h[br][0] + h[br][1] * h[br][1];
#pragma unroll
        for (int o = 16; o; o >>= 1) ss += __shfl_xor_sync(0xffffffffu, ss, o);
        float nrm = fmaxf(sqrtf(ss), 1e-12f);
        float sc = mask[br] / nrm;
        fin[w][br * 64 + lane]      = fmaxf(h[br][0] * sc, 0.f);
        fin[w][br * 64 + 32 + lane] = fmaxf(h[br][1] * sc, 0.f);
    }
    __syncwarp();

    float v0 = b2s[lane];
    float v1 = (lane < 8) ? b2s[lane + 32] : -1e30f;
    for (int k = 0; k < 192; k++) {
        float f = fin[w][k];
        v0 += f * W2s[k * NCLASS + lane];
        if (lane < 8) v1 += f * W2s[k * NCLASS + lane + 32];
    }
    float mx = fmaxf(v0, v1);
#pragma unroll
    for (int o = 16; o; o >>= 1) mx = fmaxf(mx, __shfl_xor_sync(0xffffffffu, mx, o));
    float se = expf(v0 - mx) + ((lane < 8) ? expf(v1 - mx) : 0.f);
#pragma unroll
    for (int o = 16; o; o >>= 1) se += __shfl_xor_sync(0xffffffffu, se, o);
    float lse = mx + logf(se);
    out[(size_t)n * NCLASS + lane] = v0 - lse;
    if (lane < 8) out[(size_t)n * NCLASS + 32 + lane] = v1 - lse;
}

// ---------------- launch ----------------
extern "C" void kernel_launch(void* const* d_in, const int* in_sizes, int n_in,
                              void* d_out, int out_size) {
    const float* x       = (const float*)d_in[0];
    const float* adj_att = (const float*)d_in[1];
    const float* adjs    = (const float*)d_in[2];
    const float* W1      = (const float*)d_in[3];
    const float* b1      = (const float*)d_in[4];
    const float* WQ      = (const float*)d_in[5];
    const float* bQ      = (const float*)d_in[6];
    const float* WK      = (const float*)d_in[7];
    const float* bK      = (const float*)d_in[8];
    const float* att     = (const float*)d_in[9];
    const float* W2      = (const float*)d_in[10];
    const float* b2      = (const float*)d_in[11];
    float* out = (float*)d_out;

    cudaFuncSetAttribute(k_hatt, cudaFuncAttributeMaxDynamicSharedMemorySize, HT_SMEM);
    cudaFuncSetAttribute(k_qk, cudaFuncAttributeMaxDynamicSharedMemorySize, QK_SMEM);
    cudaFuncSetAttribute(k_attn, cudaFuncAttributeMaxDynamicSharedMemorySize, AT_SMEM);

    k_fc1<<<dim3(64, 3), 256>>>(x, W1, b1);
    k_hatt<<<dim3(64, 8), 128, HT_SMEM>>>(adj_att);
    k_qk<<<dim3(64, 2), 256, QK_SMEM>>>(WQ, bQ, WK, bK);
    k_attn<<<dim3(64, 8, 2), 128, AT_SMEM>>>(adjs);
    k_final<<<512, 256>>>(att, W2, b2, out);
}

// round 12
// speedup vs baseline: 1.0145x; 1.0145x over previous
#include <cuda_runtime.h>
#include <cuda_bf16.h>
#include <math.h>
#include <stdint.h>

#define NN 4096
#define NFEAT 256
#define NHID 64
#define NCLASS 40

// ---------------- scratch ----------------
__device__ float g_H0[NN * 64];
__device__ __align__(16) __nv_bfloat16 g_HT_hi[128 * NN];   // [b*64+d][ctx]
__device__ __align__(16) __nv_bfloat16 g_HT_lo[128 * NN];
__device__ float g_part[4 * NN * 128];                      // split-K(4) partials
__device__ __align__(16) __nv_bfloat16 g_Q_hi[2 * NN * 64];
__device__ __align__(16) __nv_bfloat16 g_Q_lo[2 * NN * 64];
__device__ __align__(16) __nv_bfloat16 g_K_hi[2 * NN * 64];
__device__ __align__(16) __nv_bfloat16 g_K_lo[2 * NN * 64];
__device__ float g_apart[2 * 8 * NN * 64];

// ---------------- helpers ----------------
__device__ __forceinline__ uint32_t smem_u32(const void* p) {
    uint32_t a;
    asm("{ .reg .u64 t; cvta.to.shared.u64 t, %1; cvt.u32.u64 %0, t; }" : "=r"(a) : "l"(p));
    return a;
}
#define CP_ASYNC16(dst, src) \
    asm volatile("cp.async.ca.shared.global [%0], [%1], 16;" :: "r"(dst), "l"(src))
#define CP_COMMIT() asm volatile("cp.async.commit_group;" ::: "memory")
#define CP_WAIT0() asm volatile("cp.async.wait_group 0;" ::: "memory")

__device__ __forceinline__ void ldsm4(uint32_t& r0, uint32_t& r1, uint32_t& r2, uint32_t& r3,
                                      uint32_t addr) {
    asm volatile("ldmatrix.sync.aligned.m8n8.x4.shared.b16 {%0,%1,%2,%3}, [%4];"
                 : "=r"(r0), "=r"(r1), "=r"(r2), "=r"(r3) : "r"(addr));
}
__device__ __forceinline__ void split_bf16(float v, __nv_bfloat16& hi, __nv_bfloat16& lo) {
    hi = __float2bfloat16(v);
    lo = __float2bfloat16(v - __bfloat162float(hi));
}
__device__ __forceinline__ uint32_t pack2(__nv_bfloat16 a, __nv_bfloat16 b) {
    return (uint32_t)__bfloat16_as_ushort(a) | ((uint32_t)__bfloat16_as_ushort(b) << 16);
}
__device__ __forceinline__ void splitp(float2 v, uint32_t& hi, uint32_t& lo) {
    __nv_bfloat16 h0, l0, h1, l1;
    split_bf16(v.x, h0, l0);
    split_bf16(v.y, h1, l1);
    hi = pack2(h0, h1);
    lo = pack2(l0, l1);
}
__device__ __forceinline__ void mma16816(float d[4], const uint32_t a[4], const uint32_t b[2]) {
    asm volatile(
        "mma.sync.aligned.m16n8k16.row.col.f32.bf16.bf16.f32 "
        "{%0,%1,%2,%3}, {%4,%5,%6,%7}, {%8,%9}, {%0,%1,%2,%3};\n"
        : "+f"(d[0]), "+f"(d[1]), "+f"(d[2]), "+f"(d[3])
        : "r"(a[0]), "r"(a[1]), "r"(a[2]), "r"(a[3]), "r"(b[0]), "r"(b[1]));
}

#define STB 144
__device__ __forceinline__ void load_frag8(uint32_t bh[8][2], uint32_t bl[8][2],
                                           uint32_t hiB, uint32_t loB, int kc, int ldro) {
#pragma unroll
    for (int p = 0; p < 4; p++) {
        uint32_t a1 = hiB + (uint32_t)(p * 16) * STB + kc * 32 + ldro;
        ldsm4(bh[2 * p][0], bh[2 * p][1], bh[2 * p + 1][0], bh[2 * p + 1][1], a1);
        uint32_t a2 = loB + (uint32_t)(p * 16) * STB + kc * 32 + ldro;
        ldsm4(bl[2 * p][0], bl[2 * p][1], bl[2 * p + 1][0], bl[2 * p + 1][1], a2);
    }
}

// ---------------- kernel 1: h_i = x @ W1[i] + b1[i], coalesced transposed store ------
__global__ void k_fc1(const float* __restrict__ x, const float* __restrict__ W1,
                      const float* __restrict__ b1) {
    int br = blockIdx.y;
    int row0 = blockIdx.x * 64;
    __shared__ float As[16][65];
    __shared__ float Bs[16][64];
    __shared__ float hs[64][65];
    const float* W = W1 + br * NFEAT * NHID;
    int t = threadIdx.x;
    int ty = t >> 4, tx = t & 15;
    float acc[4][4] = {};
    for (int k0 = 0; k0 < NFEAT; k0 += 16) {
        int r = t >> 2, kk4 = (t & 3) * 4;
        float4 av = *(const float4*)(x + (size_t)(row0 + r) * NFEAT + k0 + kk4);
        As[kk4 + 0][r] = av.x; As[kk4 + 1][r] = av.y;
        As[kk4 + 2][r] = av.z; As[kk4 + 3][r] = av.w;
        int bk = t >> 4, bo = (t & 15) * 4;
        *(float4*)&Bs[bk][bo] = *(const float4*)(W + (size_t)(k0 + bk) * NHID + bo);
        __syncthreads();
#pragma unroll
        for (int kk = 0; kk < 16; kk++) {
            float a[4], b[4];
#pragma unroll
            for (int i = 0; i < 4; i++) a[i] = As[kk][ty * 4 + i];
#pragma unroll
            for (int j = 0; j < 4; j++) b[j] = Bs[kk][tx * 4 + j];
#pragma unroll
            for (int i = 0; i < 4; i++)
#pragma unroll
                for (int j = 0; j < 4; j++) acc[i][j] += a[i] * b[j];
        }
        __syncthreads();
    }
    const float* bias = b1 + br * NHID;
    if (br == 0) {
#pragma unroll
        for (int i = 0; i < 4; i++) {
            int row = row0 + ty * 4 + i;
#pragma unroll
            for (int j = 0; j < 4; j++) {
                int o = tx * 4 + j;
                g_H0[(size_t)row * 64 + o] = acc[i][j] + bias[o];
            }
        }
    } else {
#pragma unroll
        for (int i = 0; i < 4; i++)
#pragma unroll
            for (int j = 0; j < 4; j++)
                hs[tx * 4 + j][ty * 4 + i] = acc[i][j] + bias[tx * 4 + j];
        __syncthreads();
        int o = t >> 2, ch = (t & 3) * 16;
        uint32_t hp[8], lp[8];
#pragma unroll
        for (int k = 0; k < 8; k++)
            splitp(make_float2(hs[o][ch + 2 * k], hs[o][ch + 2 * k + 1]), hp[k], lp[k]);
        size_t base = (size_t)((br - 1) * 64 + o) * NN + row0 + ch;
        *(uint4*)(g_HT_hi + base) = make_uint4(hp[0], hp[1], hp[2], hp[3]);
        *(uint4*)(g_HT_hi + base + 8) = make_uint4(hp[4], hp[5], hp[6], hp[7]);
        *(uint4*)(g_HT_lo + base) = make_uint4(lp[0], lp[1], lp[2], lp[3]);
        *(uint4*)(g_HT_lo + base + 8) = make_uint4(lp[4], lp[5], lp[6], lp[7]);
    }
}

// ---------------- kernel 2: HMMA split-K(4) of adj_att @ [h1|h2] ----------------
// grid (32, 4), 256 thr. K-chunk 1024 (16 subs of 64). Warp layout as R8.
#define HT_TILE (128 * STB)
#define HT_ADJ_OFF (2 * HT_TILE)
#define HT_ADJ_ST 68
#define HT_BUF (HT_ADJ_OFF + 128 * HT_ADJ_ST * 4)
#define HT_SMEM (2 * HT_BUF)
__device__ __forceinline__ void hatt_prefetch(uint32_t bufb,
                                              const float* __restrict__ adj_att,
                                              int row0, int c0, int t) {
    const __nv_bfloat16* Bh = g_HT_hi;
    const __nv_bfloat16* Bl = g_HT_lo;
#pragma unroll
    for (int i = 0; i < 8; i++) {
        int cid = i * 256 + t;
        int half = cid >> 10, rem = cid & 1023;
        int row = rem >> 3, ch = rem & 7;
        const __nv_bfloat16* src = (half == 0 ? Bh : Bl) + (size_t)row * NN + c0 + ch * 8;
        uint32_t dst = bufb + half * HT_TILE + row * STB + ch * 16;
        CP_ASYNC16(dst, src);
    }
#pragma unroll
    for (int i = 0; i < 8; i++) {
        int cid = i * 256 + t;
        int row = cid >> 4, ch = cid & 15;
        const float* src = adj_att + (size_t)(row0 + row) * NN + c0 + ch * 4;
        uint32_t dst = bufb + HT_ADJ_OFF + (uint32_t)(row * HT_ADJ_ST + ch * 4) * 4;
        CP_ASYNC16(dst, src);
    }
}
__global__ void __launch_bounds__(256) k_hatt(const float* __restrict__ adj_att) {
    extern __shared__ char smc[];
    uint32_t sb = smem_u32(smc);
    int t = threadIdx.x, w = t >> 5, lane = t & 31;
    int g = lane >> 2, tig = lane & 3;
    int ldro = (((lane >> 4) & 1) * 8 + (lane & 7)) * STB + ((lane >> 3) & 1) * 16;
    int row0 = blockIdx.x * 128, kbase = blockIdx.y * 1024;
    int wm = (w & 3) * 32, wn = (w >> 2) * 64;
    float acc[2][8][4] = {};

    hatt_prefetch(sb, adj_att, row0, kbase, t);
    CP_COMMIT();

    for (int sub = 0; sub < 16; sub++) {
        uint32_t bufo = (sub & 1) ? HT_BUF : 0;
        CP_WAIT0();
        __syncthreads();
        if (sub < 15) {
            hatt_prefetch(sb + (bufo ^ HT_BUF), adj_att, row0, kbase + (sub + 1) * 64, t);
            CP_COMMIT();
        }
        const float* ADJ = (const float*)(smc + bufo + HT_ADJ_OFF);
        uint32_t bhiB = sb + bufo + (uint32_t)wn * STB;
        uint32_t bloB = bhiB + HT_TILE;
        uint32_t bh[2][8][2], bl[2][8][2];
        load_frag8(bh[0], bl[0], bhiB, bloB, 0, ldro);
#pragma unroll
        for (int kc = 0; kc < 4; kc++) {
            int cur = kc & 1;
            if (kc < 3) load_frag8(bh[cur ^ 1], bl[cur ^ 1], bhiB, bloB, kc + 1, ldro);
            int kcol = kc * 16 + 2 * tig;
            uint32_t ah[2][4], al[2][4];
#pragma unroll
            for (int mt = 0; mt < 2; mt++) {
                int ar = wm + mt * 16;
                splitp(*(const float2*)(ADJ + (ar + g) * HT_ADJ_ST + kcol), ah[mt][0], al[mt][0]);
                splitp(*(const float2*)(ADJ + (ar + g + 8) * HT_ADJ_ST + kcol), ah[mt][1], al[mt][1]);
                splitp(*(const float2*)(ADJ + (ar + g) * HT_ADJ_ST + kcol + 8), ah[mt][2], al[mt][2]);
                splitp(*(const float2*)(ADJ + (ar + g + 8) * HT_ADJ_ST + kcol + 8), ah[mt][3], al[mt][3]);
            }
#pragma unroll
            for (int nt = 0; nt < 8; nt++)
#pragma unroll
                for (int mt = 0; mt < 2; mt++) mma16816(acc[mt][nt], ah[mt], bh[cur][nt]);
#pragma unroll
            for (int nt = 0; nt < 8; nt++)
#pragma unroll
                for (int mt = 0; mt < 2; mt++) mma16816(acc[mt][nt], ah[mt], bl[cur][nt]);
#pragma unroll
            for (int nt = 0; nt < 8; nt++)
#pragma unroll
                for (int mt = 0; mt < 2; mt++) mma16816(acc[mt][nt], al[mt], bh[cur][nt]);
        }
    }
    float* outp = g_part + (size_t)blockIdx.y * NN * 128;
#pragma unroll
    for (int mt = 0; mt < 2; mt++)
#pragma unroll
        for (int nt = 0; nt < 8; nt++) {
            int r = row0 + wm + mt * 16 + g;
            int c = wn + nt * 8 + 2 * tig;
            *(float2*)(outp + (size_t)r * 128 + c) = make_float2(acc[mt][nt][0], acc[mt][nt][1]);
            *(float2*)(outp + (size_t)(r + 8) * 128 + c) = make_float2(acc[mt][nt][2], acc[mt][nt][3]);
        }
}

// ---------------- kernel 3: reduce 4 partials + Q/K = hatt @ W + b ----------------
#define QK_SMEM (64 * 65 * 4 + 128 * 4 + 2 * 64 * 64 * 4)
__global__ void __launch_bounds__(256) k_qk(const float* __restrict__ WQ,
                                            const float* __restrict__ bQ,
                                            const float* __restrict__ WK,
                                            const float* __restrict__ bK) {
    extern __shared__ char smc[];
    float* As = (float*)smc;
    float* biasS = As + 64 * 65;
    float* Ws = biasS + 128;
    int row0 = blockIdx.x * 64;
    int b = blockIdx.y;
    int t = threadIdx.x;
#pragma unroll
    for (int i = 0; i < 4; i++) {
        int idx = i * 1024 + t * 4;
        int m = idx >> 6, k = idx & 63;
        float4 acc = make_float4(0.f, 0.f, 0.f, 0.f);
#pragma unroll
        for (int s = 0; s < 4; s++) {
            float4 v = *(const float4*)(g_part + ((size_t)s * NN + row0 + m) * 128 + b * 64 + k);
            acc.x += v.x; acc.y += v.y; acc.z += v.z; acc.w += v.w;
        }
        float* p = As + m * 65 + k;
        p[0] = acc.x; p[1] = acc.y; p[2] = acc.z; p[3] = acc.w;
    }
#pragma unroll
    for (int i = 0; i < 4; i++) {
        int idx = i * 1024 + t * 4;
        *(float4*)(Ws + idx) = *(const float4*)(WQ + (size_t)b * 4096 + idx);
        *(float4*)(Ws + 4096 + idx) = *(const float4*)(WK + (size_t)b * 4096 + idx);
    }
    if (t < 64) biasS[t] = bQ[b * 64 + t];
    else if (t < 128) biasS[t] = bK[b * 64 + t - 64];
    __syncthreads();

    int h = t >> 7, dg = (t >> 6) & 1, m = t & 63;
    const float* Wf = Ws + h * 4096;
    float acc[32];
#pragma unroll
    for (int o = 0; o < 32; o++) acc[o] = biasS[h * 64 + dg * 32 + o];
    for (int k = 0; k < 64; k++) {
        float a = As[m * 65 + k];
#pragma unroll
        for (int o4 = 0; o4 < 8; o4++) {
            float4 wv = *(const float4*)(Wf + k * 64 + dg * 32 + o4 * 4);
            acc[o4 * 4 + 0] += a * wv.x;
            acc[o4 * 4 + 1] += a * wv.y;
            acc[o4 * 4 + 2] += a * wv.z;
            acc[o4 * 4 + 3] += a * wv.w;
        }
    }
    uint32_t hp[16], lp[16];
#pragma unroll
    for (int o2 = 0; o2 < 16; o2++)
        splitp(make_float2(acc[o2 * 2], acc[o2 * 2 + 1]), hp[o2], lp[o2]);
    size_t base = ((size_t)b * NN + row0 + m) * 64 + dg * 32;
    __nv_bfloat16* dhi = (h == 0) ? g_Q_hi : g_K_hi;
    __nv_bfloat16* dlo = (h == 0) ? g_Q_lo : g_K_lo;
#pragma unroll
    for (int q = 0; q < 4; q++) {
        *(uint4*)(dhi + base + q * 8) = make_uint4(hp[q*4], hp[q*4+1], hp[q*4+2], hp[q*4+3]);
        *(uint4*)(dlo + base + q * 8) = make_uint4(lp[q*4], lp[q*4+1], lp[q*4+2], lp[q*4+3]);
    }
}

// ---------------- kernel 4: HMMA fused attention (R8), adj via registers ----------
// grid (32 rowblk, 8 chunk, 2 branch), 256 thr. Warp w: rows w*16..+15, all 64 cols.
// SMEM: only K/H hi/lo tiles (4 x 9216), double-buffered = 73728 B.
#define AT_TILE (64 * STB)
#define AT_BUF (4 * AT_TILE)             /* 36864 */
#define AT_SMEM (2 * AT_BUF)             /* 73728 */
__device__ __forceinline__ void attn_prefetch(uint32_t bufb,
    const __nv_bfloat16* __restrict__ Kh, const __nv_bfloat16* __restrict__ Kl,
    const __nv_bfloat16* __restrict__ Hh, const __nv_bfloat16* __restrict__ Hl,
    int c0, int t) {
#pragma unroll
    for (int i = 0; i < 8; i++) {
        int cid = i * 256 + t;
        int tile = cid >> 9, rem = cid & 511;
        int row = rem >> 3, ch = rem & 7;
        const __nv_bfloat16* src;
        if (tile == 0)      src = Kh + (size_t)(c0 + row) * 64 + ch * 8;
        else if (tile == 1) src = Kl + (size_t)(c0 + row) * 64 + ch * 8;
        else if (tile == 2) src = Hh + (size_t)row * NN + c0 + ch * 8;
        else                src = Hl + (size_t)row * NN + c0 + ch * 8;
        uint32_t dst = bufb + tile * AT_TILE + row * STB + ch * 16;
        CP_ASYNC16(dst, src);
    }
}
__global__ void __launch_bounds__(256) k_attn(const float* __restrict__ adjs) {
    extern __shared__ char smc[];
    uint32_t sb = smem_u32(smc);
    int t = threadIdx.x, w = t >> 5, lane = t & 31;
    int g = lane >> 2, tig = lane & 3;
    int ldro = (((lane >> 4) & 1) * 8 + (lane & 7)) * STB + ((lane >> 3) & 1) * 16;
    int row0 = blockIdx.x * 128;
    int chunk = blockIdx.y;
    int b = blockIdx.z;
    const float* adjM = adjs + (size_t)b * NN * NN;
    const __nv_bfloat16* Qh = g_Q_hi + (size_t)b * NN * 64;
    const __nv_bfloat16* Ql = g_Q_lo + (size_t)b * NN * 64;
    const __nv_bfloat16* Kh = g_K_hi + (size_t)b * NN * 64;
    const __nv_bfloat16* Kl = g_K_lo + (size_t)b * NN * 64;
    const __nv_bfloat16* Hh = g_HT_hi + (size_t)b * 64 * NN;
    const __nv_bfloat16* Hl = g_HT_lo + (size_t)b * 64 * NN;

    attn_prefetch(sb, Kh, Kl, Hh, Hl, chunk * 512, t);
    CP_COMMIT();

    // adj row pointers for this thread's two fragment rows
    const float* adjR0 = adjM + (size_t)(row0 + w * 16 + g) * NN;
    const float* adjR8 = adjM + (size_t)(row0 + w * 16 + g + 8) * NN;

    // persistent Q fragments (rows w*16..+15, k=d 0..63)
    uint32_t qh[4][4], ql[4][4];
    {
        int qr = row0 + w * 16;
#pragma unroll
        for (int kc = 0; kc < 4; kc++) {
            int kcol = kc * 16 + 2 * tig;
            qh[kc][0] = *(const uint32_t*)(Qh + (size_t)(qr + g) * 64 + kcol);
            qh[kc][1] = *(const uint32_t*)(Qh + (size_t)(qr + g + 8) * 64 + kcol);
            qh[kc][2] = *(const uint32_t*)(Qh + (size_t)(qr + g) * 64 + kcol + 8);
            qh[kc][3] = *(const uint32_t*)(Qh + (size_t)(qr + g + 8) * 64 + kcol + 8);
            ql[kc][0] = *(const uint32_t*)(Ql + (size_t)(qr + g) * 64 + kcol);
            ql[kc][1] = *(const uint32_t*)(Ql + (size_t)(qr + g + 8) * 64 + kcol);
            ql[kc][2] = *(const uint32_t*)(Ql + (size_t)(qr + g) * 64 + kcol + 8);
            ql[kc][3] = *(const uint32_t*)(Ql + (size_t)(qr + g + 8) * 64 + kcol + 8);
        }
    }

    float oacc[8][4] = {};
    for (int sub = 0; sub < 8; sub++) {
        int c0 = chunk * 512 + sub * 64;
        uint32_t bufo = (sub & 1) ? AT_BUF : 0;
        CP_WAIT0();
        __syncthreads();
        if (sub < 7) {
            attn_prefetch(sb + (bufo ^ AT_BUF), Kh, Kl, Hh, Hl, c0 + 64, t);
            CP_COMMIT();
        }
        uint32_t khiB = sb + bufo, kloB = khiB + AT_TILE;
        uint32_t hhiB = kloB + AT_TILE, hloB = hhiB + AT_TILE;

        // issue adj global loads for this thread's 8x(2x2) elements; consumed at repack
        float2 areg0[8], areg8[8];
#pragma unroll
        for (int nt = 0; nt < 8; nt++) {
            int j0 = c0 + nt * 8 + 2 * tig;
            areg0[nt] = *(const float2*)(adjR0 + j0);
            areg8[nt] = *(const float2*)(adjR8 + j0);
        }

        uint32_t bh[2][8][2], bl[2][8][2];

        // ---- S = Q @ K^T, fragments pipelined one kc ahead ----
        float sacc[8][4] = {};
        load_frag8(bh[0], bl[0], khiB, kloB, 0, ldro);
#pragma unroll
        for (int kc = 0; kc < 4; kc++) {
            int cur = kc & 1;
            if (kc < 3) load_frag8(bh[cur ^ 1], bl[cur ^ 1], khiB, kloB, kc + 1, ldro);
#pragma unroll
            for (int nt = 0; nt < 8; nt++) mma16816(sacc[nt], qh[kc], bh[cur][nt]);
#pragma unroll
            for (int nt = 0; nt < 8; nt++) mma16816(sacc[nt], qh[kc], bl[cur][nt]);
#pragma unroll
            for (int nt = 0; nt < 8; nt++) mma16816(sacc[nt], ql[kc], bh[cur][nt]);
        }

        // prefetch O-phase kc=0 fragments; LDS overlaps the repack ALU below
        load_frag8(bh[0], bl[0], hhiB, hloB, 0, ldro);

        // ---- P = S .* adj (regs), repack C-frag -> A-frag ----
        uint32_t phi[4][4], plo[4][4];
#pragma unroll
        for (int nt = 0; nt < 8; nt++) {
            uint32_t h01, l01, h23, l23;
            splitp(make_float2(sacc[nt][0] * areg0[nt].x, sacc[nt][1] * areg0[nt].y), h01, l01);
            splitp(make_float2(sacc[nt][2] * areg8[nt].x, sacc[nt][3] * areg8[nt].y), h23, l23);
            int kc2 = nt >> 1;
            if ((nt & 1) == 0) {
                phi[kc2][0] = h01; phi[kc2][1] = h23;
                plo[kc2][0] = l01; plo[kc2][1] = l23;
            } else {
                phi[kc2][2] = h01; phi[kc2][3] = h23;
                plo[kc2][2] = l01; plo[kc2][3] = l23;
            }
        }

        // ---- O += P @ H, fragments pipelined one kc ahead ----
#pragma unroll
        for (int kc = 0; kc < 4; kc++) {
            int cur = kc & 1;
            if (kc < 3) load_frag8(bh[cur ^ 1], bl[cur ^ 1], hhiB, hloB, kc + 1, ldro);
#pragma unroll
            for (int nt = 0; nt < 8; nt++) mma16816(oacc[nt], phi[kc], bh[cur][nt]);
#pragma unroll
            for (int nt = 0; nt < 8; nt++) mma16816(oacc[nt], phi[kc], bl[cur][nt]);
#pragma unroll
            for (int nt = 0; nt < 8; nt++) mma16816(oacc[nt], plo[kc], bh[cur][nt]);
        }
    }

    float* outp = g_apart + ((size_t)(b * 8 + chunk) * NN + row0) * 64;
#pragma unroll
    for (int nt = 0; nt < 8; nt++) {
        int r = w * 16 + g;
        int c = nt * 8 + 2 * tig;
        *(float2*)(outp + (size_t)r * 64 + c) = make_float2(oacc[nt][0], oacc[nt][1]);
        *(float2*)(outp + (size_t)(r + 8) * 64 + c) = make_float2(oacc[nt][2], oacc[nt][3]);
    }
}

// ---------------- kernel 5: reduce + normalize + mask + relu + fc2 + log_softmax --------
__global__ void k_final(const float* __restrict__ att, const float* __restrict__ W2,
                        const float* __restrict__ b2, float* __restrict__ out) {
    __shared__ float W2s[192 * NCLASS];
    __shared__ float b2s[NCLASS];
    __shared__ float fin[8][192];
    int t = threadIdx.x;
    for (int i = t; i < 192 * NCLASS; i += 256) W2s[i] = W2[i];
    if (t < NCLASS) b2s[t] = b2[t];

    float a0 = att[0], a1 = att[1], a2 = att[2];
    float am = fmaxf(a0, fmaxf(a1, a2));
    float e0 = expf(a0 - am), e1 = expf(a1 - am), e2 = expf(a2 - am);
    float inv = 1.0f / (e0 + e1 + e2);
    float mask[3] = {e0 * inv, e1 * inv, e2 * inv};

    int w = t >> 5, lane = t & 31;
    int n = blockIdx.x * 8 + w;

    float h[3][2];
    h[0][0] = g_H0[(size_t)n * 64 + lane];
    h[0][1] = g_H0[(size_t)n * 64 + 32 + lane];
#pragma unroll
    for (int b = 0; b < 2; b++) {
        float s0 = 0.f, s1 = 0.f;
#pragma unroll
        for (int c = 0; c < 8; c++) {
            const float* p = g_apart + ((size_t)(b * 8 + c) * NN + n) * 64;
            s0 += p[lane];
            s1 += p[32 + lane];
        }
        h[1 + b][0] = s0;
        h[1 + b][1] = s1;
    }
    __syncthreads();

#pragma unroll
    for (int br = 0; br < 3; br++) {
        float ss = h[br][0] * h[br][0] + h[br][1] * h[br][1];
#pragma unroll
        for (int o = 16; o; o >>= 1) ss += __shfl_xor_sync(0xffffffffu, ss, o);
        float nrm = fmaxf(sqrtf(ss), 1e-12f);
        float sc = mask[br] / nrm;
        fin[w][br * 64 + lane]      = fmaxf(h[br][0] * sc, 0.f);
        fin[w][br * 64 + 32 + lane] = fmaxf(h[br][1] * sc, 0.f);
    }
    __syncwarp();

    float v0 = b2s[lane];
    float v1 = (lane < 8) ? b2s[lane + 32] : -1e30f;
    for (int k = 0; k < 192; k++) {
        float f = fin[w][k];
        v0 += f * W2s[k * NCLASS + lane];
        if (lane < 8) v1 += f * W2s[k * NCLASS + lane + 32];
    }
    float mx = fmaxf(v0, v1);
#pragma unroll
    for (int o = 16; o; o >>= 1) mx = fmaxf(mx, __shfl_xor_sync(0xffffffffu, mx, o));
    float se = expf(v0 - mx) + ((lane < 8) ? expf(v1 - mx) : 0.f);
#pragma unroll
    for (int o = 16; o; o >>= 1) se += __shfl_xor_sync(0xffffffffu, se, o);
    float lse = mx + logf(se);
    out[(size_t)n * NCLASS + lane] = v0 - lse;
    if (lane < 8) out[(size_t)n * NCLASS + 32 + lane] = v1 - lse;
}

// ---------------- launch ----------------
extern "C" void kernel_launch(void* const* d_in, const int* in_sizes, int n_in,
                              void* d_out, int out_size) {
    const float* x       = (const float*)d_in[0];
    const float* adj_att = (const float*)d_in[1];
    const float* adjs    = (const float*)d_in[2];
    const float* W1      = (const float*)d_in[3];
    const float* b1      = (const float*)d_in[4];
    const float* WQ      = (const float*)d_in[5];
    const float* bQ      = (const float*)d_in[6];
    const float* WK      = (const float*)d_in[7];
    const float* bK      = (const float*)d_in[8];
    const float* att     = (const float*)d_in[9];
    const float* W2      = (const float*)d_in[10];
    const float* b2      = (const float*)d_in[11];
    float* out = (float*)d_out;

    cudaFuncSetAttribute(k_hatt, cudaFuncAttributeMaxDynamicSharedMemorySize, HT_SMEM);
    cudaFuncSetAttribute(k_qk, cudaFuncAttributeMaxDynamicSharedMemorySize, QK_SMEM);
    cudaFuncSetAttribute(k_attn, cudaFuncAttributeMaxDynamicSharedMemorySize, AT_SMEM);

    k_fc1<<<dim3(64, 3), 256>>>(x, W1, b1);
    k_hatt<<<dim3(32, 4), 256, HT_SMEM>>>(adj_att);
    k_qk<<<dim3(64, 2), 256, QK_SMEM>>>(WQ, bQ, WK, bK);
    k_attn<<<dim3(32, 8, 2), 256, AT_SMEM>>>(adjs);
    k_final<<<512, 256>>>(att, W2, b2, out);
}

// round 14
// speedup vs baseline: 1.2904x; 1.2719x over previous
#include <cuda_runtime.h>
#include <cuda_fp16.h>
#include <math.h>
#include <stdint.h>

#define NN 4096
#define NFEAT 256
#define NHID 64
#define NCLASS 40
#define PSC 0.00390625f   /* 2^-8 */
#define OSC 256.0f

// ---------------- scratch ----------------
__device__ float g_H0[NN * 64];
__device__ __align__(16) __half g_HT_hi[128 * NN];   // [b*64+d][ctx]
__device__ __align__(16) __half g_HT_lo[128 * NN];
__device__ float g_part[4 * NN * 128];               // split-K(4) partials
__device__ __align__(16) __half g_Q[2 * NN * 64];    // fp16 hi only
__device__ __align__(16) __half g_K_hi[2 * NN * 64];
__device__ __align__(16) __half g_K_lo[2 * NN * 64];
__device__ float g_apart[2 * 8 * NN * 64];

// ---------------- helpers ----------------
__device__ __forceinline__ uint32_t smem_u32(const void* p) {
    uint32_t a;
    asm("{ .reg .u64 t; cvta.to.shared.u64 t, %1; cvt.u32.u64 %0, t; }" : "=r"(a) : "l"(p));
    return a;
}
#define CP_ASYNC16(dst, src) \
    asm volatile("cp.async.ca.shared.global [%0], [%1], 16;" :: "r"(dst), "l"(src))
#define CP_COMMIT() asm volatile("cp.async.commit_group;" ::: "memory")
#define CP_WAIT0() asm volatile("cp.async.wait_group 0;" ::: "memory")

__device__ __forceinline__ void ldsm4(uint32_t& r0, uint32_t& r1, uint32_t& r2, uint32_t& r3,
                                      uint32_t addr) {
    asm volatile("ldmatrix.sync.aligned.m8n8.x4.shared.b16 {%0,%1,%2,%3}, [%4];"
                 : "=r"(r0), "=r"(r1), "=r"(r2), "=r"(r3) : "r"(addr));
}
__device__ __forceinline__ uint32_t pack2h(__half a, __half b) {
    return (uint32_t)__half_as_ushort(a) | ((uint32_t)__half_as_ushort(b) << 16);
}
// fp16 hi/lo split of an fp32 value
__device__ __forceinline__ void split_h(float v, __half& hi, __half& lo) {
    hi = __float2half_rn(v);
    lo = __float2half_rn(v - __half2float(hi));
}
__device__ __forceinline__ void splitph(float2 v, uint32_t& hi, uint32_t& lo) {
    __half h0, l0, h1, l1;
    split_h(v.x, h0, l0);
    split_h(v.y, h1, l1);
    hi = pack2h(h0, h1);
    lo = pack2h(l0, l1);
}
// plain fp16 pack of two fp32 (no lo)
__device__ __forceinline__ uint32_t packh2(float2 v) {
    return pack2h(__float2half_rn(v.x), __float2half_rn(v.y));
}
__device__ __forceinline__ void mma16816(float d[4], const uint32_t a[4], const uint32_t b[2]) {
    asm volatile(
        "mma.sync.aligned.m16n8k16.row.col.f32.f16.f16.f32 "
        "{%0,%1,%2,%3}, {%4,%5,%6,%7}, {%8,%9}, {%0,%1,%2,%3};\n"
        : "+f"(d[0]), "+f"(d[1]), "+f"(d[2]), "+f"(d[3])
        : "r"(a[0]), "r"(a[1]), "r"(a[2]), "r"(a[3]), "r"(b[0]), "r"(b[1]));
}

#define STB 144
__device__ __forceinline__ void load_frag8(uint32_t bh[8][2], uint32_t bl[8][2],
                                           uint32_t hiB, uint32_t loB, int kc, int ldro) {
#pragma unroll
    for (int p = 0; p < 4; p++) {
        uint32_t a1 = hiB + (uint32_t)(p * 16) * STB + kc * 32 + ldro;
        ldsm4(bh[2 * p][0], bh[2 * p][1], bh[2 * p + 1][0], bh[2 * p + 1][1], a1);
        uint32_t a2 = loB + (uint32_t)(p * 16) * STB + kc * 32 + ldro;
        ldsm4(bl[2 * p][0], bl[2 * p][1], bl[2 * p + 1][0], bl[2 * p + 1][1], a2);
    }
}

// ---------------- kernel 1: h_i = x @ W1[i] + b1[i], coalesced transposed store ------
__global__ void k_fc1(const float* __restrict__ x, const float* __restrict__ W1,
                      const float* __restrict__ b1) {
    int br = blockIdx.y;
    int row0 = blockIdx.x * 64;
    __shared__ float As[16][65];
    __shared__ float Bs[16][64];
    __shared__ float hs[64][65];
    const float* W = W1 + br * NFEAT * NHID;
    int t = threadIdx.x;
    int ty = t >> 4, tx = t & 15;
    float acc[4][4] = {};
    for (int k0 = 0; k0 < NFEAT; k0 += 16) {
        int r = t >> 2, kk4 = (t & 3) * 4;
        float4 av = *(const float4*)(x + (size_t)(row0 + r) * NFEAT + k0 + kk4);
        As[kk4 + 0][r] = av.x; As[kk4 + 1][r] = av.y;
        As[kk4 + 2][r] = av.z; As[kk4 + 3][r] = av.w;
        int bk = t >> 4, bo = (t & 15) * 4;
        *(float4*)&Bs[bk][bo] = *(const float4*)(W + (size_t)(k0 + bk) * NHID + bo);
        __syncthreads();
#pragma unroll
        for (int kk = 0; kk < 16; kk++) {
            float a[4], b[4];
#pragma unroll
            for (int i = 0; i < 4; i++) a[i] = As[kk][ty * 4 + i];
#pragma unroll
            for (int j = 0; j < 4; j++) b[j] = Bs[kk][tx * 4 + j];
#pragma unroll
            for (int i = 0; i < 4; i++)
#pragma unroll
                for (int j = 0; j < 4; j++) acc[i][j] += a[i] * b[j];
        }
        __syncthreads();
    }
    const float* bias = b1 + br * NHID;
    if (br == 0) {
#pragma unroll
        for (int i = 0; i < 4; i++) {
            int row = row0 + ty * 4 + i;
#pragma unroll
            for (int j = 0; j < 4; j++) {
                int o = tx * 4 + j;
                g_H0[(size_t)row * 64 + o] = acc[i][j] + bias[o];
            }
        }
    } else {
#pragma unroll
        for (int i = 0; i < 4; i++)
#pragma unroll
            for (int j = 0; j < 4; j++)
                hs[tx * 4 + j][ty * 4 + i] = acc[i][j] + bias[tx * 4 + j];
        __syncthreads();
        int o = t >> 2, ch = (t & 3) * 16;
        uint32_t hp[8], lp[8];
#pragma unroll
        for (int k = 0; k < 8; k++)
            splitph(make_float2(hs[o][ch + 2 * k], hs[o][ch + 2 * k + 1]), hp[k], lp[k]);
        size_t base = (size_t)((br - 1) * 64 + o) * NN + row0 + ch;
        *(uint4*)(g_HT_hi + base) = make_uint4(hp[0], hp[1], hp[2], hp[3]);
        *(uint4*)(g_HT_hi + base + 8) = make_uint4(hp[4], hp[5], hp[6], hp[7]);
        *(uint4*)(g_HT_lo + base) = make_uint4(lp[0], lp[1], lp[2], lp[3]);
        *(uint4*)(g_HT_lo + base + 8) = make_uint4(lp[4], lp[5], lp[6], lp[7]);
    }
}

// ---------------- kernel 2: HMMA split-K(4) of adj_att @ [h1|h2], fp16 2-pass --------
// grid (32, 4), 256 thr. K-chunk 1024 (16 subs of 64). A = adj fp16 (hi only).
#define HT_TILE (128 * STB)
#define HT_ADJ_OFF (2 * HT_TILE)
#define HT_ADJ_ST 68
#define HT_BUF (HT_ADJ_OFF + 128 * HT_ADJ_ST * 4)
#define HT_SMEM (2 * HT_BUF)
__device__ __forceinline__ void hatt_prefetch(uint32_t bufb,
                                              const float* __restrict__ adj_att,
                                              int row0, int c0, int t) {
    const __half* Bh = g_HT_hi;
    const __half* Bl = g_HT_lo;
#pragma unroll
    for (int i = 0; i < 8; i++) {
        int cid = i * 256 + t;
        int half_ = cid >> 10, rem = cid & 1023;
        int row = rem >> 3, ch = rem & 7;
        const __half* src = (half_ == 0 ? Bh : Bl) + (size_t)row * NN + c0 + ch * 8;
        uint32_t dst = bufb + half_ * HT_TILE + row * STB + ch * 16;
        CP_ASYNC16(dst, src);
    }
#pragma unroll
    for (int i = 0; i < 8; i++) {
        int cid = i * 256 + t;
        int row = cid >> 4, ch = cid & 15;
        const float* src = adj_att + (size_t)(row0 + row) * NN + c0 + ch * 4;
        uint32_t dst = bufb + HT_ADJ_OFF + (uint32_t)(row * HT_ADJ_ST + ch * 4) * 4;
        CP_ASYNC16(dst, src);
    }
}
__global__ void __launch_bounds__(256) k_hatt(const float* __restrict__ adj_att) {
    extern __shared__ char smc[];
    uint32_t sb = smem_u32(smc);
    int t = threadIdx.x, w = t >> 5, lane = t & 31;
    int g = lane >> 2, tig = lane & 3;
    int ldro = (((lane >> 4) & 1) * 8 + (lane & 7)) * STB + ((lane >> 3) & 1) * 16;
    int row0 = blockIdx.x * 128, kbase = blockIdx.y * 1024;
    int wm = (w & 3) * 32, wn = (w >> 2) * 64;
    float acc[2][8][4] = {};

    hatt_prefetch(sb, adj_att, row0, kbase, t);
    CP_COMMIT();

    for (int sub = 0; sub < 16; sub++) {
        uint32_t bufo = (sub & 1) ? HT_BUF : 0;
        CP_WAIT0();
        __syncthreads();
        if (sub < 15) {
            hatt_prefetch(sb + (bufo ^ HT_BUF), adj_att, row0, kbase + (sub + 1) * 64, t);
            CP_COMMIT();
        }
        const float* ADJ = (const float*)(smc + bufo + HT_ADJ_OFF);
        uint32_t bhiB = sb + bufo + (uint32_t)wn * STB;
        uint32_t bloB = bhiB + HT_TILE;
        uint32_t bh[2][8][2], bl[2][8][2];
        load_frag8(bh[0], bl[0], bhiB, bloB, 0, ldro);
#pragma unroll
        for (int kc = 0; kc < 4; kc++) {
            int cur = kc & 1;
            if (kc < 3) load_frag8(bh[cur ^ 1], bl[cur ^ 1], bhiB, bloB, kc + 1, ldro);
            int kcol = kc * 16 + 2 * tig;
            uint32_t ah[2][4];
#pragma unroll
            for (int mt = 0; mt < 2; mt++) {
                int ar = wm + mt * 16;
                ah[mt][0] = packh2(*(const float2*)(ADJ + (ar + g) * HT_ADJ_ST + kcol));
                ah[mt][1] = packh2(*(const float2*)(ADJ + (ar + g + 8) * HT_ADJ_ST + kcol));
                ah[mt][2] = packh2(*(const float2*)(ADJ + (ar + g) * HT_ADJ_ST + kcol + 8));
                ah[mt][3] = packh2(*(const float2*)(ADJ + (ar + g + 8) * HT_ADJ_ST + kcol + 8));
            }
#pragma unroll
            for (int nt = 0; nt < 8; nt++)
#pragma unroll
                for (int mt = 0; mt < 2; mt++) mma16816(acc[mt][nt], ah[mt], bh[cur][nt]);
#pragma unroll
            for (int nt = 0; nt < 8; nt++)
#pragma unroll
                for (int mt = 0; mt < 2; mt++) mma16816(acc[mt][nt], ah[mt], bl[cur][nt]);
        }
    }
    float* outp = g_part + (size_t)blockIdx.y * NN * 128;
#pragma unroll
    for (int mt = 0; mt < 2; mt++)
#pragma unroll
        for (int nt = 0; nt < 8; nt++) {
            int r = row0 + wm + mt * 16 + g;
            int c = wn + nt * 8 + 2 * tig;
            *(float2*)(outp + (size_t)r * 128 + c) = make_float2(acc[mt][nt][0], acc[mt][nt][1]);
            *(float2*)(outp + (size_t)(r + 8) * 128 + c) = make_float2(acc[mt][nt][2], acc[mt][nt][3]);
        }
}

// ---------------- kernel 3: reduce 4 partials + Q/K = hatt @ W + b ----------------
// Q stored fp16 hi only; K stored fp16 hi+lo.
#define QK_SMEM (64 * 65 * 4 + 128 * 4 + 2 * 64 * 64 * 4)
__global__ void __launch_bounds__(256) k_qk(const float* __restrict__ WQ,
                                            const float* __restrict__ bQ,
                                            const float* __restrict__ WK,
                                            const float* __restrict__ bK) {
    extern __shared__ char smc[];
    float* As = (float*)smc;
    float* biasS = As + 64 * 65;
    float* Ws = biasS + 128;
    int row0 = blockIdx.x * 64;
    int b = blockIdx.y;
    int t = threadIdx.x;
#pragma unroll
    for (int i = 0; i < 4; i++) {
        int idx = i * 1024 + t * 4;
        int m = idx >> 6, k = idx & 63;
        float4 acc = make_float4(0.f, 0.f, 0.f, 0.f);
#pragma unroll
        for (int s = 0; s < 4; s++) {
            float4 v = *(const float4*)(g_part + ((size_t)s * NN + row0 + m) * 128 + b * 64 + k);
            acc.x += v.x; acc.y += v.y; acc.z += v.z; acc.w += v.w;
        }
        float* p = As + m * 65 + k;
        p[0] = acc.x; p[1] = acc.y; p[2] = acc.z; p[3] = acc.w;
    }
#pragma unroll
    for (int i = 0; i < 4; i++) {
        int idx = i * 1024 + t * 4;
        *(float4*)(Ws + idx) = *(const float4*)(WQ + (size_t)b * 4096 + idx);
        *(float4*)(Ws + 4096 + idx) = *(const float4*)(WK + (size_t)b * 4096 + idx);
    }
    if (t < 64) biasS[t] = bQ[b * 64 + t];
    else if (t < 128) biasS[t] = bK[b * 64 + t - 64];
    __syncthreads();

    int h = t >> 7, dg = (t >> 6) & 1, m = t & 63;
    const float* Wf = Ws + h * 4096;
    float acc[32];
#pragma unroll
    for (int o = 0; o < 32; o++) acc[o] = biasS[h * 64 + dg * 32 + o];
    for (int k = 0; k < 64; k++) {
        float a = As[m * 65 + k];
#pragma unroll
        for (int o4 = 0; o4 < 8; o4++) {
            float4 wv = *(const float4*)(Wf + k * 64 + dg * 32 + o4 * 4);
            acc[o4 * 4 + 0] += a * wv.x;
            acc[o4 * 4 + 1] += a * wv.y;
            acc[o4 * 4 + 2] += a * wv.z;
            acc[o4 * 4 + 3] += a * wv.w;
        }
    }
    size_t base = ((size_t)b * NN + row0 + m) * 64 + dg * 32;
    if (h == 0) {
        uint32_t hp[16];
#pragma unroll
        for (int o2 = 0; o2 < 16; o2++)
            hp[o2] = packh2(make_float2(acc[o2 * 2], acc[o2 * 2 + 1]));
#pragma unroll
        for (int q = 0; q < 4; q++)
            *(uint4*)(g_Q + base + q * 8) = make_uint4(hp[q*4], hp[q*4+1], hp[q*4+2], hp[q*4+3]);
    } else {
        uint32_t hp[16], lp[16];
#pragma unroll
        for (int o2 = 0; o2 < 16; o2++)
            splitph(make_float2(acc[o2 * 2], acc[o2 * 2 + 1]), hp[o2], lp[o2]);
#pragma unroll
        for (int q = 0; q < 4; q++) {
            *(uint4*)(g_K_hi + base + q * 8) = make_uint4(hp[q*4], hp[q*4+1], hp[q*4+2], hp[q*4+3]);
            *(uint4*)(g_K_lo + base + q * 8) = make_uint4(lp[q*4], lp[q*4+1], lp[q*4+2], lp[q*4+3]);
        }
    }
}

// ---------------- kernel 4: HMMA fused attention (R8 layout), fp16 2-pass ----------
// grid (32 rowblk, 8 chunk, 2 branch), 256 thr. Warp w: rows w*16..+15, all 64 cols.
#define AT_TILE (64 * STB)
#define AT_ADJ_OFF (4 * AT_TILE)
#define AT_ADJ_ST 68
#define AT_BUF (AT_ADJ_OFF + 128 * AT_ADJ_ST * 4)   /* 71680 */
#define AT_SMEM (2 * AT_BUF)
__device__ __forceinline__ void attn_prefetch(uint32_t bufb,
    const __half* __restrict__ Kh, const __half* __restrict__ Kl,
    const __half* __restrict__ Hh, const __half* __restrict__ Hl,
    const float* __restrict__ adjM, int row0, int c0, int t) {
#pragma unroll
    for (int i = 0; i < 8; i++) {
        int cid = i * 256 + t;
        int tile = cid >> 9, rem = cid & 511;
        int row = rem >> 3, ch = rem & 7;
        const __half* src;
        if (tile == 0)      src = Kh + (size_t)(c0 + row) * 64 + ch * 8;
        else if (tile == 1) src = Kl + (size_t)(c0 + row) * 64 + ch * 8;
        else if (tile == 2) src = Hh + (size_t)row * NN + c0 + ch * 8;
        else                src = Hl + (size_t)row * NN + c0 + ch * 8;
        uint32_t dst = bufb + tile * AT_TILE + row * STB + ch * 16;
        CP_ASYNC16(dst, src);
    }
#pragma unroll
    for (int i = 0; i < 8; i++) {
        int cid = i * 256 + t;
        int row = cid >> 4, ch = cid & 15;
        const float* src = adjM + (size_t)(row0 + row) * NN + c0 + ch * 4;
        uint32_t dst = bufb + AT_ADJ_OFF + (uint32_t)(row * AT_ADJ_ST + ch * 4) * 4;
        CP_ASYNC16(dst, src);
    }
}
__global__ void __launch_bounds__(256) k_attn(const float* __restrict__ adjs) {
    extern __shared__ char smc[];
    uint32_t sb = smem_u32(smc);
    int t = threadIdx.x, w = t >> 5, lane = t & 31;
    int g = lane >> 2, tig = lane & 3;
    int ldro = (((lane >> 4) & 1) * 8 + (lane & 7)) * STB + ((lane >> 3) & 1) * 16;
    int row0 = blockIdx.x * 128;
    int chunk = blockIdx.y;
    int b = blockIdx.z;
    const float* adjM = adjs + (size_t)b * NN * NN;
    const __half* Qg = g_Q + (size_t)b * NN * 64;
    const __half* Kh = g_K_hi + (size_t)b * NN * 64;
    const __half* Kl = g_K_lo + (size_t)b * NN * 64;
    const __half* Hh = g_HT_hi + (size_t)b * 64 * NN;
    const __half* Hl = g_HT_lo + (size_t)b * 64 * NN;

    attn_prefetch(sb, Kh, Kl, Hh, Hl, adjM, row0, chunk * 512, t);
    CP_COMMIT();

    // persistent Q fragments, fp16 hi only (rows w*16..+15, k=d 0..63)
    uint32_t qh[4][4];
    {
        int qr = row0 + w * 16;
#pragma unroll
        for (int kc = 0; kc < 4; kc++) {
            int kcol = kc * 16 + 2 * tig;
            qh[kc][0] = *(const uint32_t*)(Qg + (size_t)(qr + g) * 64 + kcol);
            qh[kc][1] = *(const uint32_t*)(Qg + (size_t)(qr + g + 8) * 64 + kcol);
            qh[kc][2] = *(const uint32_t*)(Qg + (size_t)(qr + g) * 64 + kcol + 8);
            qh[kc][3] = *(const uint32_t*)(Qg + (size_t)(qr + g + 8) * 64 + kcol + 8);
        }
    }

    float oacc[8][4] = {};
    for (int sub = 0; sub < 8; sub++) {
        uint32_t bufo = (sub & 1) ? AT_BUF : 0;
        CP_WAIT0();
        __syncthreads();
        if (sub < 7) {
            attn_prefetch(sb + (bufo ^ AT_BUF), Kh, Kl, Hh, Hl, adjM,
                          row0, chunk * 512 + (sub + 1) * 64, t);
            CP_COMMIT();
        }
        uint32_t khiB = sb + bufo, kloB = khiB + AT_TILE;
        uint32_t hhiB = kloB + AT_TILE, hloB = hhiB + AT_TILE;
        const float* ADJ = (const float*)(smc + bufo + AT_ADJ_OFF);

        uint32_t bh[2][8][2], bl[2][8][2];

        // ---- S = Q @ K^T (2 passes), fragments pipelined one kc ahead ----
        float sacc[8][4] = {};
        load_frag8(bh[0], bl[0], khiB, kloB, 0, ldro);
#pragma unroll
        for (int kc = 0; kc < 4; kc++) {
            int cur = kc & 1;
            if (kc < 3) load_frag8(bh[cur ^ 1], bl[cur ^ 1], khiB, kloB, kc + 1, ldro);
#pragma unroll
            for (int nt = 0; nt < 8; nt++) mma16816(sacc[nt], qh[kc], bh[cur][nt]);
#pragma unroll
            for (int nt = 0; nt < 8; nt++) mma16816(sacc[nt], qh[kc], bl[cur][nt]);
        }

        // prefetch O-phase kc=0 fragments; LDS overlaps the repack ALU below
        load_frag8(bh[0], bl[0], hhiB, hloB, 0, ldro);

        // ---- P = (S .* adj) * 2^-8, pack to fp16 A-frags ----
        uint32_t phi[4][4];
        int mr = w * 16;
#pragma unroll
        for (int nt = 0; nt < 8; nt++) {
            int j0 = nt * 8 + 2 * tig;
            float2 a01 = *(const float2*)(ADJ + (mr + g) * AT_ADJ_ST + j0);
            float2 a23 = *(const float2*)(ADJ + (mr + g + 8) * AT_ADJ_ST + j0);
            uint32_t h01 = packh2(make_float2(sacc[nt][0] * a01.x * PSC,
                                              sacc[nt][1] * a01.y * PSC));
            uint32_t h23 = packh2(make_float2(sacc[nt][2] * a23.x * PSC,
                                              sacc[nt][3] * a23.y * PSC));
            int kc2 = nt >> 1;
            if ((nt & 1) == 0) { phi[kc2][0] = h01; phi[kc2][1] = h23; }
            else               { phi[kc2][2] = h01; phi[kc2][3] = h23; }
        }

        // ---- O += P @ H (2 passes), fragments pipelined one kc ahead ----
#pragma unroll
        for (int kc = 0; kc < 4; kc++) {
            int cur = kc & 1;
            if (kc < 3) load_frag8(bh[cur ^ 1], bl[cur ^ 1], hhiB, hloB, kc + 1, ldro);
#pragma unroll
            for (int nt = 0; nt < 8; nt++) mma16816(oacc[nt], phi[kc], bh[cur][nt]);
#pragma unroll
            for (int nt = 0; nt < 8; nt++) mma16816(oacc[nt], phi[kc], bl[cur][nt]);
        }
    }

    float* outp = g_apart + ((size_t)(b * 8 + chunk) * NN + row0) * 64;
#pragma unroll
    for (int nt = 0; nt < 8; nt++) {
        int r = w * 16 + g;
        int c = nt * 8 + 2 * tig;
        *(float2*)(outp + (size_t)r * 64 + c) =
            make_float2(oacc[nt][0] * OSC, oacc[nt][1] * OSC);
        *(float2*)(outp + (size_t)(r + 8) * 64 + c) =
            make_float2(oacc[nt][2] * OSC, oacc[nt][3] * OSC);
    }
}

// ---------------- kernel 5: reduce + normalize + mask + relu + fc2 + log_softmax --------
__global__ void k_final(const float* __restrict__ att, const float* __restrict__ W2,
                        const float* __restrict__ b2, float* __restrict__ out) {
    __shared__ float W2s[192 * NCLASS];
    __shared__ float b2s[NCLASS];
    __shared__ float fin[8][192];
    int t = threadIdx.x;
    for (int i = t; i < 192 * NCLASS; i += 256) W2s[i] = W2[i];
    if (t < NCLASS) b2s[t] = b2[t];

    float a0 = att[0], a1 = att[1], a2 = att[2];
    float am = fmaxf(a0, fmaxf(a1, a2));
    float e0 = expf(a0 - am), e1 = expf(a1 - am), e2 = expf(a2 - am);
    float inv = 1.0f / (e0 + e1 + e2);
    float mask[3] = {e0 * inv, e1 * inv, e2 * inv};

    int w = t >> 5, lane = t & 31;
    int n = blockIdx.x * 8 + w;

    float h[3][2];
    h[0][0] = g_H0[(size_t)n * 64 + lane];
    h[0][1] = g_H0[(size_t)n * 64 + 32 + lane];
#pragma unroll
    for (int b = 0; b < 2; b++) {
        float s0 = 0.f, s1 = 0.f;
#pragma unroll
        for (int c = 0; c < 8; c++) {
            const float* p = g_apart + ((size_t)(b * 8 + c) * NN + n) * 64;
            s0 += p[lane];
            s1 += p[32 + lane];
        }
        h[1 + b][0] = s0;
        h[1 + b][1] = s1;
    }
    __syncthreads();

#pragma unroll
    for (int br = 0; br < 3; br++) {
        float ss = h[br][0] * h[br][0] + h[br][1] * h[br][1];
#pragma unroll
        for (int o = 16; o; o >>= 1) ss += __shfl_xor_sync(0xffffffffu, ss, o);
        float nrm = fmaxf(sqrtf(ss), 1e-12f);
        float sc = mask[br] / nrm;
        fin[w][br * 64 + lane]      = fmaxf(h[br][0] * sc, 0.f);
        fin[w][br * 64 + 32 + lane] = fmaxf(h[br][1] * sc, 0.f);
    }
    __syncwarp();

    float v0 = b2s[lane];
    float v1 = (lane < 8) ? b2s[lane + 32] : -1e30f;
    for (int k = 0; k < 192; k++) {
        float f = fin[w][k];
        v0 += f * W2s[k * NCLASS + lane];
        if (lane < 8) v1 += f * W2s[k * NCLASS + lane + 32];
    }
    float mx = fmaxf(v0, v1);
#pragma unroll
    for (int o = 16; o; o >>= 1) mx = fmaxf(mx, __shfl_xor_sync(0xffffffffu, mx, o));
    float se = expf(v0 - mx) + ((lane < 8) ? expf(v1 - mx) : 0.f);
#pragma unroll
    for (int o = 16; o; o >>= 1) se += __shfl_xor_sync(0xffffffffu, se, o);
    float lse = mx + logf(se);
    out[(size_t)n * NCLASS + lane] = v0 - lse;
    if (lane < 8) out[(size_t)n * NCLASS + 32 + lane] = v1 - lse;
}

// ---------------- launch ----------------
extern "C" void kernel_launch(void* const* d_in, const int* in_sizes, int n_in,
                              void* d_out, int out_size) {
    const float* x       = (const float*)d_in[0];
    const float* adj_att = (const float*)d_in[1];
    const float* adjs    = (const float*)d_in[2];
    const float* W1      = (const float*)d_in[3];
    const float* b1      = (const float*)d_in[4];
    const float* WQ      = (const float*)d_in[5];
    const float* bQ      = (const float*)d_in[6];
    const float* WK      = (const float*)d_in[7];
    const float* bK      = (const float*)d_in[8];
    const float* att     = (const float*)d_in[9];
    const float* W2      = (const float*)d_in[10];
    const float* b2      = (const float*)d_in[11];
    float* out = (float*)d_out;

    cudaFuncSetAttribute(k_hatt, cudaFuncAttributeMaxDynamicSharedMemorySize, HT_SMEM);
    cudaFuncSetAttribute(k_qk, cudaFuncAttributeMaxDynamicSharedMemorySize, QK_SMEM);
    cudaFuncSetAttribute(k_attn, cudaFuncAttributeMaxDynamicSharedMemorySize, AT_SMEM);

    k_fc1<<<dim3(64, 3), 256>>>(x, W1, b1);
    k_hatt<<<dim3(32, 4), 256, HT_SMEM>>>(adj_att);
    k_qk<<<dim3(64, 2), 256, QK_SMEM>>>(WQ, bQ, WK, bK);
    k_attn<<<dim3(32, 8, 2), 256, AT_SMEM>>>(adjs);
    k_final<<<512, 256>>>(att, W2, b2, out);
}

// round 16
// speedup vs baseline: 1.4735x; 1.1419x over previous
#include <cuda_runtime.h>
#include <cuda_fp16.h>
#include <math.h>
#include <stdint.h>

#define NN 4096
#define NFEAT 256
#define NHID 64
#define NCLASS 40
#define PSC 0.00390625f   /* 2^-8 */
#define OSC 256.0f

// ---------------- scratch ----------------
__device__ float g_H0[NN * 64];
__device__ __align__(16) __half g_HT[128 * NN];      // [b*64+d][ctx] fp16
__device__ float g_part[4 * NN * 128];               // split-K(4) partials
__device__ __align__(16) __half g_Q[2 * NN * 64];    // fp16
__device__ __align__(16) __half g_K[2 * NN * 64];    // fp16
__device__ float g_apart[2 * 8 * NN * 64];

// ---------------- helpers ----------------
__device__ __forceinline__ uint32_t smem_u32(const void* p) {
    uint32_t a;
    asm("{ .reg .u64 t; cvta.to.shared.u64 t, %1; cvt.u32.u64 %0, t; }" : "=r"(a) : "l"(p));
    return a;
}
#define CP_ASYNC16(dst, src) \
    asm volatile("cp.async.ca.shared.global [%0], [%1], 16;" :: "r"(dst), "l"(src))
#define CP_COMMIT() asm volatile("cp.async.commit_group;" ::: "memory")
#define CP_WAIT0() asm volatile("cp.async.wait_group 0;" ::: "memory")

__device__ __forceinline__ void ldsm4(uint32_t& r0, uint32_t& r1, uint32_t& r2, uint32_t& r3,
                                      uint32_t addr) {
    asm volatile("ldmatrix.sync.aligned.m8n8.x4.shared.b16 {%0,%1,%2,%3}, [%4];"
                 : "=r"(r0), "=r"(r1), "=r"(r2), "=r"(r3) : "r"(addr));
}
__device__ __forceinline__ uint32_t pack2h(__half a, __half b) {
    return (uint32_t)__half_as_ushort(a) | ((uint32_t)__half_as_ushort(b) << 16);
}
__device__ __forceinline__ uint32_t packh2(float2 v) {
    return pack2h(__float2half_rn(v.x), __float2half_rn(v.y));
}
__device__ __forceinline__ void mma16816(float d[4], const uint32_t a[4], const uint32_t b[2]) {
    asm volatile(
        "mma.sync.aligned.m16n8k16.row.col.f32.f16.f16.f32 "
        "{%0,%1,%2,%3}, {%4,%5,%6,%7}, {%8,%9}, {%0,%1,%2,%3};\n"
        : "+f"(d[0]), "+f"(d[1]), "+f"(d[2]), "+f"(d[3])
        : "r"(a[0]), "r"(a[1]), "r"(a[2]), "r"(a[3]), "r"(b[0]), "r"(b[1]));
}

#define STB 144
// Load 8 n-tiles of one kc group (single tile, 4 ldsm4)
__device__ __forceinline__ void load_frag8s(uint32_t bh[8][2], uint32_t base,
                                            int kc, int ldro) {
#pragma unroll
    for (int p = 0; p < 4; p++) {
        uint32_t a1 = base + (uint32_t)(p * 16) * STB + kc * 32 + ldro;
        ldsm4(bh[2 * p][0], bh[2 * p][1], bh[2 * p + 1][0], bh[2 * p + 1][1], a1);
    }
}

// ---------------- kernel 1: h_i = x @ W1[i] + b1[i], coalesced transposed store ------
__global__ void k_fc1(const float* __restrict__ x, const float* __restrict__ W1,
                      const float* __restrict__ b1) {
    int br = blockIdx.y;
    int row0 = blockIdx.x * 64;
    __shared__ float As[16][65];
    __shared__ float Bs[16][64];
    __shared__ float hs[64][65];
    const float* W = W1 + br * NFEAT * NHID;
    int t = threadIdx.x;
    int ty = t >> 4, tx = t & 15;
    float acc[4][4] = {};
    for (int k0 = 0; k0 < NFEAT; k0 += 16) {
        int r = t >> 2, kk4 = (t & 3) * 4;
        float4 av = *(const float4*)(x + (size_t)(row0 + r) * NFEAT + k0 + kk4);
        As[kk4 + 0][r] = av.x; As[kk4 + 1][r] = av.y;
        As[kk4 + 2][r] = av.z; As[kk4 + 3][r] = av.w;
        int bk = t >> 4, bo = (t & 15) * 4;
        *(float4*)&Bs[bk][bo] = *(const float4*)(W + (size_t)(k0 + bk) * NHID + bo);
        __syncthreads();
#pragma unroll
        for (int kk = 0; kk < 16; kk++) {
            float a[4], b[4];
#pragma unroll
            for (int i = 0; i < 4; i++) a[i] = As[kk][ty * 4 + i];
#pragma unroll
            for (int j = 0; j < 4; j++) b[j] = Bs[kk][tx * 4 + j];
#pragma unroll
            for (int i = 0; i < 4; i++)
#pragma unroll
                for (int j = 0; j < 4; j++) acc[i][j] += a[i] * b[j];
        }
        __syncthreads();
    }
    const float* bias = b1 + br * NHID;
    if (br == 0) {
#pragma unroll
        for (int i = 0; i < 4; i++) {
            int row = row0 + ty * 4 + i;
#pragma unroll
            for (int j = 0; j < 4; j++) {
                int o = tx * 4 + j;
                g_H0[(size_t)row * 64 + o] = acc[i][j] + bias[o];
            }
        }
    } else {
#pragma unroll
        for (int i = 0; i < 4; i++)
#pragma unroll
            for (int j = 0; j < 4; j++)
                hs[tx * 4 + j][ty * 4 + i] = acc[i][j] + bias[tx * 4 + j];
        __syncthreads();
        int o = t >> 2, ch = (t & 3) * 16;
        uint32_t hp[8];
#pragma unroll
        for (int k = 0; k < 8; k++)
            hp[k] = packh2(make_float2(hs[o][ch + 2 * k], hs[o][ch + 2 * k + 1]));
        size_t base = (size_t)((br - 1) * 64 + o) * NN + row0 + ch;
        *(uint4*)(g_HT + base) = make_uint4(hp[0], hp[1], hp[2], hp[3]);
        *(uint4*)(g_HT + base + 8) = make_uint4(hp[4], hp[5], hp[6], hp[7]);
    }
}

// ---------------- kernel 2: HMMA split-K(4) of adj_att @ [h1|h2], fp16 1-pass --------
// grid (32, 4), 256 thr. K-chunk 1024 (16 subs of 64).
#define HT_TILE (128 * STB)               /* 18432 */
#define HT_ADJ_OFF HT_TILE
#define HT_ADJ_ST 68
#define HT_BUF (HT_ADJ_OFF + 128 * HT_ADJ_ST * 4)   /* 53248 */
#define HT_SMEM (2 * HT_BUF)                          /* 106496 */
__device__ __forceinline__ void hatt_prefetch(uint32_t bufb,
                                              const float* __restrict__ adj_att,
                                              int row0, int c0, int t) {
    const __half* B = g_HT;
#pragma unroll
    for (int i = 0; i < 4; i++) {          // B tile: 128 rows x 8 chunks
        int cid = i * 256 + t;
        int row = cid >> 3, ch = cid & 7;
        const __half* src = B + (size_t)row * NN + c0 + ch * 8;
        uint32_t dst = bufb + row * STB + ch * 16;
        CP_ASYNC16(dst, src);
    }
#pragma unroll
    for (int i = 0; i < 8; i++) {          // adj fp32: 128 rows x 16 chunks
        int cid = i * 256 + t;
        int row = cid >> 4, ch = cid & 15;
        const float* src = adj_att + (size_t)(row0 + row) * NN + c0 + ch * 4;
        uint32_t dst = bufb + HT_ADJ_OFF + (uint32_t)(row * HT_ADJ_ST + ch * 4) * 4;
        CP_ASYNC16(dst, src);
    }
}
__global__ void __launch_bounds__(256) k_hatt(const float* __restrict__ adj_att) {
    extern __shared__ char smc[];
    uint32_t sb = smem_u32(smc);
    int t = threadIdx.x, w = t >> 5, lane = t & 31;
    int g = lane >> 2, tig = lane & 3;
    int ldro = (((lane >> 4) & 1) * 8 + (lane & 7)) * STB + ((lane >> 3) & 1) * 16;
    int row0 = blockIdx.x * 128, kbase = blockIdx.y * 1024;
    int wm = (w & 3) * 32, wn = (w >> 2) * 64;
    float acc[2][8][4] = {};

    hatt_prefetch(sb, adj_att, row0, kbase, t);
    CP_COMMIT();

    for (int sub = 0; sub < 16; sub++) {
        uint32_t bufo = (sub & 1) ? HT_BUF : 0;
        CP_WAIT0();
        __syncthreads();
        if (sub < 15) {
            hatt_prefetch(sb + (bufo ^ HT_BUF), adj_att, row0, kbase + (sub + 1) * 64, t);
            CP_COMMIT();
        }
        const float* ADJ = (const float*)(smc + bufo + HT_ADJ_OFF);
        uint32_t bB = sb + bufo + (uint32_t)wn * STB;
        uint32_t bh[2][8][2];
        load_frag8s(bh[0], bB, 0, ldro);
#pragma unroll
        for (int kc = 0; kc < 4; kc++) {
            int cur = kc & 1;
            if (kc < 3) load_frag8s(bh[cur ^ 1], bB, kc + 1, ldro);
            int kcol = kc * 16 + 2 * tig;
            uint32_t ah[2][4];
#pragma unroll
            for (int mt = 0; mt < 2; mt++) {
                int ar = wm + mt * 16;
                ah[mt][0] = packh2(*(const float2*)(ADJ + (ar + g) * HT_ADJ_ST + kcol));
                ah[mt][1] = packh2(*(const float2*)(ADJ + (ar + g + 8) * HT_ADJ_ST + kcol));
                ah[mt][2] = packh2(*(const float2*)(ADJ + (ar + g) * HT_ADJ_ST + kcol + 8));
                ah[mt][3] = packh2(*(const float2*)(ADJ + (ar + g + 8) * HT_ADJ_ST + kcol + 8));
            }
#pragma unroll
            for (int nt = 0; nt < 8; nt++)
#pragma unroll
                for (int mt = 0; mt < 2; mt++) mma16816(acc[mt][nt], ah[mt], bh[cur][nt]);
        }
    }
    float* outp = g_part + (size_t)blockIdx.y * NN * 128;
#pragma unroll
    for (int mt = 0; mt < 2; mt++)
#pragma unroll
        for (int nt = 0; nt < 8; nt++) {
            int r = row0 + wm + mt * 16 + g;
            int c = wn + nt * 8 + 2 * tig;
            *(float2*)(outp + (size_t)r * 128 + c) = make_float2(acc[mt][nt][0], acc[mt][nt][1]);
            *(float2*)(outp + (size_t)(r + 8) * 128 + c) = make_float2(acc[mt][nt][2], acc[mt][nt][3]);
        }
}

// ---------------- kernel 3: reduce 4 partials + Q/K = hatt @ W + b ----------------
#define QK_SMEM (64 * 65 * 4 + 128 * 4 + 2 * 64 * 64 * 4)
__global__ void __launch_bounds__(256) k_qk(const float* __restrict__ WQ,
                                            const float* __restrict__ bQ,
                                            const float* __restrict__ WK,
                                            const float* __restrict__ bK) {
    extern __shared__ char smc[];
    float* As = (float*)smc;
    float* biasS = As + 64 * 65;
    float* Ws = biasS + 128;
    int row0 = blockIdx.x * 64;
    int b = blockIdx.y;
    int t = threadIdx.x;
#pragma unroll
    for (int i = 0; i < 4; i++) {
        int idx = i * 1024 + t * 4;
        int m = idx >> 6, k = idx & 63;
        float4 acc = make_float4(0.f, 0.f, 0.f, 0.f);
#pragma unroll
        for (int s = 0; s < 4; s++) {
            float4 v = *(const float4*)(g_part + ((size_t)s * NN + row0 + m) * 128 + b * 64 + k);
            acc.x += v.x; acc.y += v.y; acc.z += v.z; acc.w += v.w;
        }
        float* p = As + m * 65 + k;
        p[0] = acc.x; p[1] = acc.y; p[2] = acc.z; p[3] = acc.w;
    }
#pragma unroll
    for (int i = 0; i < 4; i++) {
        int idx = i * 1024 + t * 4;
        *(float4*)(Ws + idx) = *(const float4*)(WQ + (size_t)b * 4096 + idx);
        *(float4*)(Ws + 4096 + idx) = *(const float4*)(WK + (size_t)b * 4096 + idx);
    }
    if (t < 64) biasS[t] = bQ[b * 64 + t];
    else if (t < 128) biasS[t] = bK[b * 64 + t - 64];
    __syncthreads();

    int h = t >> 7, dg = (t >> 6) & 1, m = t & 63;
    const float* Wf = Ws + h * 4096;
    float acc[32];
#pragma unroll
    for (int o = 0; o < 32; o++) acc[o] = biasS[h * 64 + dg * 32 + o];
    for (int k = 0; k < 64; k++) {
        float a = As[m * 65 + k];
#pragma unroll
        for (int o4 = 0; o4 < 8; o4++) {
            float4 wv = *(const float4*)(Wf + k * 64 + dg * 32 + o4 * 4);
            acc[o4 * 4 + 0] += a * wv.x;
            acc[o4 * 4 + 1] += a * wv.y;
            acc[o4 * 4 + 2] += a * wv.z;
            acc[o4 * 4 + 3] += a * wv.w;
        }
    }
    uint32_t hp[16];
#pragma unroll
    for (int o2 = 0; o2 < 16; o2++)
        hp[o2] = packh2(make_float2(acc[o2 * 2], acc[o2 * 2 + 1]));
    size_t base = ((size_t)b * NN + row0 + m) * 64 + dg * 32;
    __half* dst = (h == 0) ? g_Q : g_K;
#pragma unroll
    for (int q = 0; q < 4; q++)
        *(uint4*)(dst + base + q * 8) = make_uint4(hp[q*4], hp[q*4+1], hp[q*4+2], hp[q*4+3]);
}

// ---------------- kernel 4: HMMA fused attention, fp16 1-pass ----------------
// grid (32 rowblk, 8 chunk, 2 branch), 256 thr. Warp w: rows w*16..+15, all 64 cols.
#define AT_TILE (64 * STB)                /* 9216 */
#define AT_ADJ_OFF (2 * AT_TILE)          /* 18432 */
#define AT_ADJ_ST 68
#define AT_BUF (AT_ADJ_OFF + 128 * AT_ADJ_ST * 4)   /* 53248 */
#define AT_SMEM (2 * AT_BUF)                          /* 106496 */
__device__ __forceinline__ void attn_prefetch(uint32_t bufb,
    const __half* __restrict__ Kg, const __half* __restrict__ Hg,
    const float* __restrict__ adjM, int row0, int c0, int t) {
#pragma unroll
    for (int i = 0; i < 4; i++) {          // K/H tiles: 2 x 64 rows x 8 chunks
        int cid = i * 256 + t;
        int tile = cid >> 9, rem = cid & 511;
        int row = rem >> 3, ch = rem & 7;
        const __half* src = (tile == 0)
            ? Kg + (size_t)(c0 + row) * 64 + ch * 8
            : Hg + (size_t)row * NN + c0 + ch * 8;
        uint32_t dst = bufb + tile * AT_TILE + row * STB + ch * 16;
        CP_ASYNC16(dst, src);
    }
#pragma unroll
    for (int i = 0; i < 8; i++) {          // adj fp32: 128 rows x 16 chunks
        int cid = i * 256 + t;
        int row = cid >> 4, ch = cid & 15;
        const float* src = adjM + (size_t)(row0 + row) * NN + c0 + ch * 4;
        uint32_t dst = bufb + AT_ADJ_OFF + (uint32_t)(row * AT_ADJ_ST + ch * 4) * 4;
        CP_ASYNC16(dst, src);
    }
}
__global__ void __launch_bounds__(256) k_attn(const float* __restrict__ adjs) {
    extern __shared__ char smc[];
    uint32_t sb = smem_u32(smc);
    int t = threadIdx.x, w = t >> 5, lane = t & 31;
    int g = lane >> 2, tig = lane & 3;
    int ldro = (((lane >> 4) & 1) * 8 + (lane & 7)) * STB + ((lane >> 3) & 1) * 16;
    int row0 = blockIdx.x * 128;
    int chunk = blockIdx.y;
    int b = blockIdx.z;
    const float* adjM = adjs + (size_t)b * NN * NN;
    const __half* Qg = g_Q + (size_t)b * NN * 64;
    const __half* Kg = g_K + (size_t)b * NN * 64;
    const __half* Hg = g_HT + (size_t)b * 64 * NN;

    attn_prefetch(sb, Kg, Hg, adjM, row0, chunk * 512, t);
    CP_COMMIT();

    // persistent Q fragments (rows w*16..+15, k=d 0..63)
    uint32_t qh[4][4];
    {
        int qr = row0 + w * 16;
#pragma unroll
        for (int kc = 0; kc < 4; kc++) {
            int kcol = kc * 16 + 2 * tig;
            qh[kc][0] = *(const uint32_t*)(Qg + (size_t)(qr + g) * 64 + kcol);
            qh[kc][1] = *(const uint32_t*)(Qg + (size_t)(qr + g + 8) * 64 + kcol);
            qh[kc][2] = *(const uint32_t*)(Qg + (size_t)(qr + g) * 64 + kcol + 8);
            qh[kc][3] = *(const uint32_t*)(Qg + (size_t)(qr + g + 8) * 64 + kcol + 8);
        }
    }

    float oacc[8][4] = {};
    for (int sub = 0; sub < 8; sub++) {
        uint32_t bufo = (sub & 1) ? AT_BUF : 0;
        CP_WAIT0();
        __syncthreads();
        if (sub < 7) {
            attn_prefetch(sb + (bufo ^ AT_BUF), Kg, Hg, adjM,
                          row0, chunk * 512 + (sub + 1) * 64, t);
            CP_COMMIT();
        }
        uint32_t kB = sb + bufo, hB = kB + AT_TILE;
        const float* ADJ = (const float*)(smc + bufo + AT_ADJ_OFF);

        uint32_t bh[2][8][2];

        // ---- S = Q @ K^T (1 pass), fragments pipelined one kc ahead ----
        float sacc[8][4] = {};
        load_frag8s(bh[0], kB, 0, ldro);
#pragma unroll
        for (int kc = 0; kc < 4; kc++) {
            int cur = kc & 1;
            if (kc < 3) load_frag8s(bh[cur ^ 1], kB, kc + 1, ldro);
#pragma unroll
            for (int nt = 0; nt < 8; nt++) mma16816(sacc[nt], qh[kc], bh[cur][nt]);
        }

        // prefetch O-phase kc=0 fragments; LDS overlaps the repack ALU below
        load_frag8s(bh[0], hB, 0, ldro);

        // ---- P = (S .* adj) * 2^-8, pack to fp16 A-frags ----
        uint32_t phi[4][4];
        int mr = w * 16;
#pragma unroll
        for (int nt = 0; nt < 8; nt++) {
            int j0 = nt * 8 + 2 * tig;
            float2 a01 = *(const float2*)(ADJ + (mr + g) * AT_ADJ_ST + j0);
            float2 a23 = *(const float2*)(ADJ + (mr + g + 8) * AT_ADJ_ST + j0);
            uint32_t h01 = packh2(make_float2(sacc[nt][0] * a01.x * PSC,
                                              sacc[nt][1] * a01.y * PSC));
            uint32_t h23 = packh2(make_float2(sacc[nt][2] * a23.x * PSC,
                                              sacc[nt][3] * a23.y * PSC));
            int kc2 = nt >> 1;
            if ((nt & 1) == 0) { phi[kc2][0] = h01; phi[kc2][1] = h23; }
            else               { phi[kc2][2] = h01; phi[kc2][3] = h23; }
        }

        // ---- O += P @ H (1 pass), fragments pipelined one kc ahead ----
#pragma unroll
        for (int kc = 0; kc < 4; kc++) {
            int cur = kc & 1;
            if (kc < 3) load_frag8s(bh[cur ^ 1], hB, kc + 1, ldro);
#pragma unroll
            for (int nt = 0; nt < 8; nt++) mma16816(oacc[nt], phi[kc], bh[cur][nt]);
        }
    }

    float* outp = g_apart + ((size_t)(b * 8 + chunk) * NN + row0) * 64;
#pragma unroll
    for (int nt = 0; nt < 8; nt++) {
        int r = w * 16 + g;
        int c = nt * 8 + 2 * tig;
        *(float2*)(outp + (size_t)r * 64 + c) =
            make_float2(oacc[nt][0] * OSC, oacc[nt][1] * OSC);
        *(float2*)(outp + (size_t)(r + 8) * 64 + c) =
            make_float2(oacc[nt][2] * OSC, oacc[nt][3] * OSC);
    }
}

// ---------------- kernel 5: reduce + normalize + mask + relu + fc2 + log_softmax --------
__global__ void k_final(const float* __restrict__ att, const float* __restrict__ W2,
                        const float* __restrict__ b2, float* __restrict__ out) {
    __shared__ float W2s[192 * NCLASS];
    __shared__ float b2s[NCLASS];
    __shared__ float fin[8][192];
    int t = threadIdx.x;
    for (int i = t; i < 192 * NCLASS; i += 256) W2s[i] = W2[i];
    if (t < NCLASS) b2s[t] = b2[t];

    float a0 = att[0], a1 = att[1], a2 = att[2];
    float am = fmaxf(a0, fmaxf(a1, a2));
    float e0 = expf(a0 - am), e1 = expf(a1 - am), e2 = expf(a2 - am);
    float inv = 1.0f / (e0 + e1 + e2);
    float mask[3] = {e0 * inv, e1 * inv, e2 * inv};

    int w = t >> 5, lane = t & 31;
    int n = blockIdx.x * 8 + w;

    float h[3][2];
    h[0][0] = g_H0[(size_t)n * 64 + lane];
    h[0][1] = g_H0[(size_t)n * 64 + 32 + lane];
#pragma unroll
    for (int b = 0; b < 2; b++) {
        float s0 = 0.f, s1 = 0.f;
#pragma unroll
        for (int c = 0; c < 8; c++) {
            const float* p = g_apart + ((size_t)(b * 8 + c) * NN + n) * 64;
            s0 += p[lane];
            s1 += p[32 + lane];
        }
        h[1 + b][0] = s0;
        h[1 + b][1] = s1;
    }
    __syncthreads();

#pragma unroll
    for (int br = 0; br < 3; br++) {
        float ss = h[br][0] * h[br][0] + h[br][1] * h[br][1];
#pragma unroll
        for (int o = 16; o; o >>= 1) ss += __shfl_xor_sync(0xffffffffu, ss, o);
        float nrm = fmaxf(sqrtf(ss), 1e-12f);
        float sc = mask[br] / nrm;
        fin[w][br * 64 + lane]      = fmaxf(h[br][0] * sc, 0.f);
        fin[w][br * 64 + 32 + lane] = fmaxf(h[br][1] * sc, 0.f);
    }
    __syncwarp();

    float v0 = b2s[lane];
    float v1 = (lane < 8) ? b2s[lane + 32] : -1e30f;
    for (int k = 0; k < 192; k++) {
        float f = fin[w][k];
        v0 += f * W2s[k * NCLASS + lane];
        if (lane < 8) v1 += f * W2s[k * NCLASS + lane + 32];
    }
    float mx = fmaxf(v0, v1);
#pragma unroll
    for (int o = 16; o; o >>= 1) mx = fmaxf(mx, __shfl_xor_sync(0xffffffffu, mx, o));
    float se = expf(v0 - mx) + ((lane < 8) ? expf(v1 - mx) : 0.f);
#pragma unroll
    for (int o = 16; o; o >>= 1) se += __shfl_xor_sync(0xffffffffu, se, o);
    float lse = mx + logf(se);
    out[(size_t)n * NCLASS + lane] = v0 - lse;
    if (lane < 8) out[(size_t)n * NCLASS + 32 + lane] = v1 - lse;
}

// ---------------- launch ----------------
extern "C" void kernel_launch(void* const* d_in, const int* in_sizes, int n_in,
                              void* d_out, int out_size) {
    const float* x       = (const float*)d_in[0];
    const float* adj_att = (const float*)d_in[1];
    const float* adjs    = (const float*)d_in[2];
    const float* W1      = (const float*)d_in[3];
    const float* b1      = (const float*)d_in[4];
    const float* WQ      = (const float*)d_in[5];
    const float* bQ      = (const float*)d_in[6];
    const float* WK      = (const float*)d_in[7];
    const float* bK      = (const float*)d_in[8];
    const float* att     = (const float*)d_in[9];
    const float* W2      = (const float*)d_in[10];
    const float* b2      = (const float*)d_in[11];
    float* out = (float*)d_out;

    cudaFuncSetAttribute(k_hatt, cudaFuncAttributeMaxDynamicSharedMemorySize, HT_SMEM);
    cudaFuncSetAttribute(k_qk, cudaFuncAttributeMaxDynamicSharedMemorySize, QK_SMEM);
    cudaFuncSetAttribute(k_attn, cudaFuncAttributeMaxDynamicSharedMemorySize, AT_SMEM);

    k_fc1<<<dim3(64, 3), 256>>>(x, W1, b1);
    k_hatt<<<dim3(32, 4), 256, HT_SMEM>>>(adj_att);
    k_qk<<<dim3(64, 2), 256, QK_SMEM>>>(WQ, bQ, WK, bK);
    k_attn<<<dim3(32, 8, 2), 256, AT_SMEM>>>(adjs);
    k_final<<<512, 256>>>(att, W2, b2, out);
}

// round 17
// speedup vs baseline: 1.5143x; 1.0277x over previous
#include <cuda_runtime.h>
#include <cuda_fp16.h>
#include <math.h>
#include <stdint.h>

#define NN 4096
#define NFEAT 256
#define NHID 64
#define NCLASS 40
#define PSC 0.00390625f   /* 2^-8 */
#define OSC 256.0f

// ---------------- scratch ----------------
__device__ float g_H0[NN * 64];
__device__ __align__(16) __half g_HT[128 * NN];      // [b*64+d][ctx] fp16
__device__ float g_part[4 * NN * 128];               // split-K(4) partials
__device__ __align__(16) __half g_Q[2 * NN * 64];    // fp16
__device__ __align__(16) __half g_K[2 * NN * 64];    // fp16
__device__ float g_apart[2 * 8 * NN * 64];

// ---------------- helpers ----------------
__device__ __forceinline__ uint32_t smem_u32(const void* p) {
    uint32_t a;
    asm("{ .reg .u64 t; cvta.to.shared.u64 t, %1; cvt.u32.u64 %0, t; }" : "=r"(a) : "l"(p));
    return a;
}
#define CP_ASYNC16(dst, src) \
    asm volatile("cp.async.ca.shared.global [%0], [%1], 16;" :: "r"(dst), "l"(src))
#define CP_COMMIT() asm volatile("cp.async.commit_group;" ::: "memory")
#define CP_WAIT0() asm volatile("cp.async.wait_group 0;" ::: "memory")

__device__ __forceinline__ void ldsm4(uint32_t& r0, uint32_t& r1, uint32_t& r2, uint32_t& r3,
                                      uint32_t addr) {
    asm volatile("ldmatrix.sync.aligned.m8n8.x4.shared.b16 {%0,%1,%2,%3}, [%4];"
                 : "=r"(r0), "=r"(r1), "=r"(r2), "=r"(r3) : "r"(addr));
}
__device__ __forceinline__ uint32_t pack2h(__half a, __half b) {
    return (uint32_t)__half_as_ushort(a) | ((uint32_t)__half_as_ushort(b) << 16);
}
__device__ __forceinline__ uint32_t packh2(float2 v) {
    return pack2h(__float2half_rn(v.x), __float2half_rn(v.y));
}
__device__ __forceinline__ void mma16816(float d[4], const uint32_t a[4], const uint32_t b[2]) {
    asm volatile(
        "mma.sync.aligned.m16n8k16.row.col.f32.f16.f16.f32 "
        "{%0,%1,%2,%3}, {%4,%5,%6,%7}, {%8,%9}, {%0,%1,%2,%3};\n"
        : "+f"(d[0]), "+f"(d[1]), "+f"(d[2]), "+f"(d[3])
        : "r"(a[0]), "r"(a[1]), "r"(a[2]), "r"(a[3]), "r"(b[0]), "r"(b[1]));
}

#define STB 144
__device__ __forceinline__ void load_frag8s(uint32_t bh[8][2], uint32_t base,
                                            int kc, int ldro) {
#pragma unroll
    for (int p = 0; p < 4; p++) {
        uint32_t a1 = base + (uint32_t)(p * 16) * STB + kc * 32 + ldro;
        ldsm4(bh[2 * p][0], bh[2 * p][1], bh[2 * p + 1][0], bh[2 * p + 1][1], a1);
    }
}

// ---------------- kernel 1: h_i = x @ W1[i] + b1[i], coalesced transposed store ------
__global__ void k_fc1(const float* __restrict__ x, const float* __restrict__ W1,
                      const float* __restrict__ b1) {
    int br = blockIdx.y;
    int row0 = blockIdx.x * 64;
    __shared__ float As[16][65];
    __shared__ float Bs[16][64];
    __shared__ float hs[64][65];
    const float* W = W1 + br * NFEAT * NHID;
    int t = threadIdx.x;
    int ty = t >> 4, tx = t & 15;
    float acc[4][4] = {};
    for (int k0 = 0; k0 < NFEAT; k0 += 16) {
        int r = t >> 2, kk4 = (t & 3) * 4;
        float4 av = *(const float4*)(x + (size_t)(row0 + r) * NFEAT + k0 + kk4);
        As[kk4 + 0][r] = av.x; As[kk4 + 1][r] = av.y;
        As[kk4 + 2][r] = av.z; As[kk4 + 3][r] = av.w;
        int bk = t >> 4, bo = (t & 15) * 4;
        *(float4*)&Bs[bk][bo] = *(const float4*)(W + (size_t)(k0 + bk) * NHID + bo);
        __syncthreads();
#pragma unroll
        for (int kk = 0; kk < 16; kk++) {
            float a[4], b[4];
#pragma unroll
            for (int i = 0; i < 4; i++) a[i] = As[kk][ty * 4 + i];
#pragma unroll
            for (int j = 0; j < 4; j++) b[j] = Bs[kk][tx * 4 + j];
#pragma unroll
            for (int i = 0; i < 4; i++)
#pragma unroll
                for (int j = 0; j < 4; j++) acc[i][j] += a[i] * b[j];
        }
        __syncthreads();
    }
    const float* bias = b1 + br * NHID;
    if (br == 0) {
#pragma unroll
        for (int i = 0; i < 4; i++) {
            int row = row0 + ty * 4 + i;
#pragma unroll
            for (int j = 0; j < 4; j++) {
                int o = tx * 4 + j;
                g_H0[(size_t)row * 64 + o] = acc[i][j] + bias[o];
            }
        }
    } else {
#pragma unroll
        for (int i = 0; i < 4; i++)
#pragma unroll
            for (int j = 0; j < 4; j++)
                hs[tx * 4 + j][ty * 4 + i] = acc[i][j] + bias[tx * 4 + j];
        __syncthreads();
        int o = t >> 2, ch = (t & 3) * 16;
        uint32_t hp[8];
#pragma unroll
        for (int k = 0; k < 8; k++)
            hp[k] = packh2(make_float2(hs[o][ch + 2 * k], hs[o][ch + 2 * k + 1]));
        size_t base = (size_t)((br - 1) * 64 + o) * NN + row0 + ch;
        *(uint4*)(g_HT + base) = make_uint4(hp[0], hp[1], hp[2], hp[3]);
        *(uint4*)(g_HT + base + 8) = make_uint4(hp[4], hp[5], hp[6], hp[7]);
    }
}

// ---------------- kernel 2: HMMA split-K(4), 128 thr, warp = 64 rows x 64 cols --------
// grid (32, 4), 128 thr. Warp w: rows (w&1)*64 (4 m-tiles), cols (w>>1)*64 (8 n-tiles).
#define HT_TILE (128 * STB)               /* 18432 */
#define HT_ADJ_OFF HT_TILE
#define HT_ADJ_ST 68
#define HT_BUF (HT_ADJ_OFF + 128 * HT_ADJ_ST * 4)   /* 53248 */
#define HT_SMEM (2 * HT_BUF)                          /* 106496 */
__device__ __forceinline__ void hatt_prefetch(uint32_t bufb,
                                              const float* __restrict__ adj_att,
                                              int row0, int c0, int t) {
    const __half* B = g_HT;
#pragma unroll
    for (int i = 0; i < 8; i++) {          // B tile: 128 rows x 8 chunks
        int cid = i * 128 + t;
        int row = cid >> 3, ch = cid & 7;
        const __half* src = B + (size_t)row * NN + c0 + ch * 8;
        uint32_t dst = bufb + row * STB + ch * 16;
        CP_ASYNC16(dst, src);
    }
#pragma unroll
    for (int i = 0; i < 16; i++) {         // adj fp32: 128 rows x 16 chunks
        int cid = i * 128 + t;
        int row = cid >> 4, ch = cid & 15;
        const float* src = adj_att + (size_t)(row0 + row) * NN + c0 + ch * 4;
        uint32_t dst = bufb + HT_ADJ_OFF + (uint32_t)(row * HT_ADJ_ST + ch * 4) * 4;
        CP_ASYNC16(dst, src);
    }
}
__global__ void __launch_bounds__(128) k_hatt(const float* __restrict__ adj_att) {
    extern __shared__ char smc[];
    uint32_t sb = smem_u32(smc);
    int t = threadIdx.x, w = t >> 5, lane = t & 31;
    int g = lane >> 2, tig = lane & 3;
    int ldro = (((lane >> 4) & 1) * 8 + (lane & 7)) * STB + ((lane >> 3) & 1) * 16;
    int row0 = blockIdx.x * 128, kbase = blockIdx.y * 1024;
    int wm = (w & 1) * 64, wn = (w >> 1) * 64;
    float acc[4][8][4] = {};

    hatt_prefetch(sb, adj_att, row0, kbase, t);
    CP_COMMIT();

    for (int sub = 0; sub < 16; sub++) {
        uint32_t bufo = (sub & 1) ? HT_BUF : 0;
        CP_WAIT0();
        __syncthreads();
        if (sub < 15) {
            hatt_prefetch(sb + (bufo ^ HT_BUF), adj_att, row0, kbase + (sub + 1) * 64, t);
            CP_COMMIT();
        }
        const float* ADJ = (const float*)(smc + bufo + HT_ADJ_OFF);
        uint32_t bB = sb + bufo + (uint32_t)wn * STB;
        uint32_t bh[2][8][2];
        load_frag8s(bh[0], bB, 0, ldro);
#pragma unroll
        for (int kc = 0; kc < 4; kc++) {
            int cur = kc & 1;
            if (kc < 3) load_frag8s(bh[cur ^ 1], bB, kc + 1, ldro);
            int kcol = kc * 16 + 2 * tig;
            uint32_t ah[4][4];
#pragma unroll
            for (int mt = 0; mt < 4; mt++) {
                int ar = wm + mt * 16;
                ah[mt][0] = packh2(*(const float2*)(ADJ + (ar + g) * HT_ADJ_ST + kcol));
                ah[mt][1] = packh2(*(const float2*)(ADJ + (ar + g + 8) * HT_ADJ_ST + kcol));
                ah[mt][2] = packh2(*(const float2*)(ADJ + (ar + g) * HT_ADJ_ST + kcol + 8));
                ah[mt][3] = packh2(*(const float2*)(ADJ + (ar + g + 8) * HT_ADJ_ST + kcol + 8));
            }
#pragma unroll
            for (int nt = 0; nt < 8; nt++)
#pragma unroll
                for (int mt = 0; mt < 4; mt++) mma16816(acc[mt][nt], ah[mt], bh[cur][nt]);
        }
    }
    float* outp = g_part + (size_t)blockIdx.y * NN * 128;
#pragma unroll
    for (int mt = 0; mt < 4; mt++)
#pragma unroll
        for (int nt = 0; nt < 8; nt++) {
            int r = row0 + wm + mt * 16 + g;
            int c = wn + nt * 8 + 2 * tig;
            *(float2*)(outp + (size_t)r * 128 + c) = make_float2(acc[mt][nt][0], acc[mt][nt][1]);
            *(float2*)(outp + (size_t)(r + 8) * 128 + c) = make_float2(acc[mt][nt][2], acc[mt][nt][3]);
        }
}

// ---------------- kernel 3: reduce 4 partials + Q/K = hatt @ W + b ----------------
#define QK_SMEM (64 * 65 * 4 + 128 * 4 + 2 * 64 * 64 * 4)
__global__ void __launch_bounds__(256) k_qk(const float* __restrict__ WQ,
                                            const float* __restrict__ bQ,
                                            const float* __restrict__ WK,
                                            const float* __restrict__ bK) {
    extern __shared__ char smc[];
    float* As = (float*)smc;
    float* biasS = As + 64 * 65;
    float* Ws = biasS + 128;
    int row0 = blockIdx.x * 64;
    int b = blockIdx.y;
    int t = threadIdx.x;
#pragma unroll
    for (int i = 0; i < 4; i++) {
        int idx = i * 1024 + t * 4;
        int m = idx >> 6, k = idx & 63;
        float4 acc = make_float4(0.f, 0.f, 0.f, 0.f);
#pragma unroll
        for (int s = 0; s < 4; s++) {
            float4 v = *(const float4*)(g_part + ((size_t)s * NN + row0 + m) * 128 + b * 64 + k);
            acc.x += v.x; acc.y += v.y; acc.z += v.z; acc.w += v.w;
        }
        float* p = As + m * 65 + k;
        p[0] = acc.x; p[1] = acc.y; p[2] = acc.z; p[3] = acc.w;
    }
#pragma unroll
    for (int i = 0; i < 4; i++) {
        int idx = i * 1024 + t * 4;
        *(float4*)(Ws + idx) = *(const float4*)(WQ + (size_t)b * 4096 + idx);
        *(float4*)(Ws + 4096 + idx) = *(const float4*)(WK + (size_t)b * 4096 + idx);
    }
    if (t < 64) biasS[t] = bQ[b * 64 + t];
    else if (t < 128) biasS[t] = bK[b * 64 + t - 64];
    __syncthreads();

    int h = t >> 7, dg = (t >> 6) & 1, m = t & 63;
    const float* Wf = Ws + h * 4096;
    float acc[32];
#pragma unroll
    for (int o = 0; o < 32; o++) acc[o] = biasS[h * 64 + dg * 32 + o];
    for (int k = 0; k < 64; k++) {
        float a = As[m * 65 + k];
#pragma unroll
        for (int o4 = 0; o4 < 8; o4++) {
            float4 wv = *(const float4*)(Wf + k * 64 + dg * 32 + o4 * 4);
            acc[o4 * 4 + 0] += a * wv.x;
            acc[o4 * 4 + 1] += a * wv.y;
            acc[o4 * 4 + 2] += a * wv.z;
            acc[o4 * 4 + 3] += a * wv.w;
        }
    }
    uint32_t hp[16];
#pragma unroll
    for (int o2 = 0; o2 < 16; o2++)
        hp[o2] = packh2(make_float2(acc[o2 * 2], acc[o2 * 2 + 1]));
    size_t base = ((size_t)b * NN + row0 + m) * 64 + dg * 32;
    __half* dst = (h == 0) ? g_Q : g_K;
#pragma unroll
    for (int q = 0; q < 4; q++)
        *(uint4*)(dst + base + q * 8) = make_uint4(hp[q*4], hp[q*4+1], hp[q*4+2], hp[q*4+3]);
}

// ---------------- kernel 4: HMMA fused attention, 128 thr, warp = 32 rows ----------
// grid (32 rowblk, 8 chunk, 2 branch), 128 thr. Warp w: rows w*32..+31 (2 m-tiles).
#define AT_TILE (64 * STB)                /* 9216 */
#define AT_ADJ_OFF (2 * AT_TILE)          /* 18432 */
#define AT_ADJ_ST 68
#define AT_BUF (AT_ADJ_OFF + 128 * AT_ADJ_ST * 4)   /* 53248 */
#define AT_SMEM (2 * AT_BUF)                          /* 106496 */
__device__ __forceinline__ void attn_prefetch(uint32_t bufb,
    const __half* __restrict__ Kg, const __half* __restrict__ Hg,
    const float* __restrict__ adjM, int row0, int c0, int t) {
#pragma unroll
    for (int i = 0; i < 8; i++) {          // K/H tiles: 2 x 64 rows x 8 chunks
        int cid = i * 128 + t;
        int tile = cid >> 9, rem = cid & 511;
        int row = rem >> 3, ch = rem & 7;
        const __half* src = (tile == 0)
            ? Kg + (size_t)(c0 + row) * 64 + ch * 8
            : Hg + (size_t)row * NN + c0 + ch * 8;
        uint32_t dst = bufb + tile * AT_TILE + row * STB + ch * 16;
        CP_ASYNC16(dst, src);
    }
#pragma unroll
    for (int i = 0; i < 16; i++) {         // adj fp32: 128 rows x 16 chunks
        int cid = i * 128 + t;
        int row = cid >> 4, ch = cid & 15;
        const float* src = adjM + (size_t)(row0 + row) * NN + c0 + ch * 4;
        uint32_t dst = bufb + AT_ADJ_OFF + (uint32_t)(row * AT_ADJ_ST + ch * 4) * 4;
        CP_ASYNC16(dst, src);
    }
}
__global__ void __launch_bounds__(128) k_attn(const float* __restrict__ adjs) {
    extern __shared__ char smc[];
    uint32_t sb = smem_u32(smc);
    int t = threadIdx.x, w = t >> 5, lane = t & 31;
    int g = lane >> 2, tig = lane & 3;
    int ldro = (((lane >> 4) & 1) * 8 + (lane & 7)) * STB + ((lane >> 3) & 1) * 16;
    int wm = w * 32;
    int row0 = blockIdx.x * 128;
    int chunk = blockIdx.y;
    int b = blockIdx.z;
    const float* adjM = adjs + (size_t)b * NN * NN;
    const __half* Qg = g_Q + (size_t)b * NN * 64;
    const __half* Kg = g_K + (size_t)b * NN * 64;
    const __half* Hg = g_HT + (size_t)b * 64 * NN;

    attn_prefetch(sb, Kg, Hg, adjM, row0, chunk * 512, t);
    CP_COMMIT();

    // persistent Q fragments: 2 m-tiles (rows wm, wm+16), k = 0..63
    uint32_t qh[2][4][4];
#pragma unroll
    for (int mt = 0; mt < 2; mt++) {
        int qr = row0 + wm + mt * 16;
#pragma unroll
        for (int kc = 0; kc < 4; kc++) {
            int kcol = kc * 16 + 2 * tig;
            qh[mt][kc][0] = *(const uint32_t*)(Qg + (size_t)(qr + g) * 64 + kcol);
            qh[mt][kc][1] = *(const uint32_t*)(Qg + (size_t)(qr + g + 8) * 64 + kcol);
            qh[mt][kc][2] = *(const uint32_t*)(Qg + (size_t)(qr + g) * 64 + kcol + 8);
            qh[mt][kc][3] = *(const uint32_t*)(Qg + (size_t)(qr + g + 8) * 64 + kcol + 8);
        }
    }

    float oacc[2][8][4] = {};
    for (int sub = 0; sub < 8; sub++) {
        uint32_t bufo = (sub & 1) ? AT_BUF : 0;
        CP_WAIT0();
        __syncthreads();
        if (sub < 7) {
            attn_prefetch(sb + (bufo ^ AT_BUF), Kg, Hg, adjM,
                          row0, chunk * 512 + (sub + 1) * 64, t);
            CP_COMMIT();
        }
        uint32_t kB = sb + bufo, hB = kB + AT_TILE;
        const float* ADJ = (const float*)(smc + bufo + AT_ADJ_OFF);

        uint32_t bh[2][8][2];

        // ---- S = Q @ K^T, fragments pipelined one kc ahead, shared across m-tiles ----
        float sacc[2][8][4] = {};
        load_frag8s(bh[0], kB, 0, ldro);
#pragma unroll
        for (int kc = 0; kc < 4; kc++) {
            int cur = kc & 1;
            if (kc < 3) load_frag8s(bh[cur ^ 1], kB, kc + 1, ldro);
#pragma unroll
            for (int nt = 0; nt < 8; nt++)
#pragma unroll
                for (int mt = 0; mt < 2; mt++) mma16816(sacc[mt][nt], qh[mt][kc], bh[cur][nt]);
        }

        // prefetch O-phase kc=0 fragments; LDS overlaps the repack ALU below
        load_frag8s(bh[0], hB, 0, ldro);

        // ---- P = (S .* adj) * 2^-8, pack to fp16 A-frags (per m-tile) ----
        uint32_t phi[2][4][4];
#pragma unroll
        for (int mt = 0; mt < 2; mt++) {
            int mr = wm + mt * 16;
#pragma unroll
            for (int nt = 0; nt < 8; nt++) {
                int j0 = nt * 8 + 2 * tig;
                float2 a01 = *(const float2*)(ADJ + (mr + g) * AT_ADJ_ST + j0);
                float2 a23 = *(const float2*)(ADJ + (mr + g + 8) * AT_ADJ_ST + j0);
                uint32_t h01 = packh2(make_float2(sacc[mt][nt][0] * a01.x * PSC,
                                                  sacc[mt][nt][1] * a01.y * PSC));
                uint32_t h23 = packh2(make_float2(sacc[mt][nt][2] * a23.x * PSC,
                                                  sacc[mt][nt][3] * a23.y * PSC));
                int kc2 = nt >> 1;
                if ((nt & 1) == 0) { phi[mt][kc2][0] = h01; phi[mt][kc2][1] = h23; }
                else               { phi[mt][kc2][2] = h01; phi[mt][kc2][3] = h23; }
            }
        }

        // ---- O += P @ H, fragments pipelined one kc ahead, shared across m-tiles ----
#pragma unroll
        for (int kc = 0; kc < 4; kc++) {
            int cur = kc & 1;
            if (kc < 3) load_frag8s(bh[cur ^ 1], hB, kc + 1, ldro);
#pragma unroll
            for (int nt = 0; nt < 8; nt++)
#pragma unroll
                for (int mt = 0; mt < 2; mt++) mma16816(oacc[mt][nt], phi[mt][kc], bh[cur][nt]);
        }
    }

    float* outp = g_apart + ((size_t)(b * 8 + chunk) * NN + row0) * 64;
#pragma unroll
    for (int mt = 0; mt < 2; mt++)
#pragma unroll
        for (int nt = 0; nt < 8; nt++) {
            int r = wm + mt * 16 + g;
            int c = nt * 8 + 2 * tig;
            *(float2*)(outp + (size_t)r * 64 + c) =
                make_float2(oacc[mt][nt][0] * OSC, oacc[mt][nt][1] * OSC);
            *(float2*)(outp + (size_t)(r + 8) * 64 + c) =
                make_float2(oacc[mt][nt][2] * OSC, oacc[mt][nt][3] * OSC);
        }
}

// ---------------- kernel 5: reduce + normalize + mask + relu + fc2 + log_softmax --------
__global__ void k_final(const float* __restrict__ att, const float* __restrict__ W2,
                        const float* __restrict__ b2, float* __restrict__ out) {
    __shared__ float W2s[192 * NCLASS];
    __shared__ float b2s[NCLASS];
    __shared__ float fin[8][192];
    int t = threadIdx.x;
    for (int i = t; i < 192 * NCLASS; i += 256) W2s[i] = W2[i];
    if (t < NCLASS) b2s[t] = b2[t];

    float a0 = att[0], a1 = att[1], a2 = att[2];
    float am = fmaxf(a0, fmaxf(a1, a2));
    float e0 = expf(a0 - am), e1 = expf(a1 - am), e2 = expf(a2 - am);
    float inv = 1.0f / (e0 + e1 + e2);
    float mask[3] = {e0 * inv, e1 * inv, e2 * inv};

    int w = t >> 5, lane = t & 31;
    int n = blockIdx.x * 8 + w;

    float h[3][2];
    h[0][0] = g_H0[(size_t)n * 64 + lane];
    h[0][1] = g_H0[(size_t)n * 64 + 32 + lane];
#pragma unroll
    for (int b = 0; b < 2; b++) {
        float s0 = 0.f, s1 = 0.f;
#pragma unroll
        for (int c = 0; c < 8; c++) {
            const float* p = g_apart + ((size_t)(b * 8 + c) * NN + n) * 64;
            s0 += p[lane];
            s1 += p[32 + lane];
        }
        h[1 + b][0] = s0;
        h[1 + b][1] = s1;
    }
    __syncthreads();

#pragma unroll
    for (int br = 0; br < 3; br++) {
        float ss = h[br][0] * h[br][0] + h[br][1] * h[br][1];
#pragma unroll
        for (int o = 16; o; o >>= 1) ss += __shfl_xor_sync(0xffffffffu, ss, o);
        float nrm = fmaxf(sqrtf(ss), 1e-12f);
        float sc = mask[br] / nrm;
        fin[w][br * 64 + lane]      = fmaxf(h[br][0] * sc, 0.f);
        fin[w][br * 64 + 32 + lane] = fmaxf(h[br][1] * sc, 0.f);
    }
    __syncwarp();

    float v0 = b2s[lane];
    float v1 = (lane < 8) ? b2s[lane + 32] : -1e30f;
    for (int k = 0; k < 192; k++) {
        float f = fin[w][k];
        v0 += f * W2s[k * NCLASS + lane];
        if (lane < 8) v1 += f * W2s[k * NCLASS + lane + 32];
    }
    float mx = fmaxf(v0, v1);
#pragma unroll
    for (int o = 16; o; o >>= 1) mx = fmaxf(mx, __shfl_xor_sync(0xffffffffu, mx, o));
    float se = expf(v0 - mx) + ((lane < 8) ? expf(v1 - mx) : 0.f);
#pragma unroll
    for (int o = 16; o; o >>= 1) se += __shfl_xor_sync(0xffffffffu, se, o);
    float lse = mx + logf(se);
    out[(size_t)n * NCLASS + lane] = v0 - lse;
    if (lane < 8) out[(size_t)n * NCLASS + 32 + lane] = v1 - lse;
}

// ---------------- launch ----------------
extern "C" void kernel_launch(void* const* d_in, const int* in_sizes, int n_in,
                              void* d_out, int out_size) {
    const float* x       = (const float*)d_in[0];
    const float* adj_att = (const float*)d_in[1];
    const float* adjs    = (const float*)d_in[2];
    const float* W1      = (const float*)d_in[3];
    const float* b1      = (const float*)d_in[4];
    const float* WQ      = (const float*)d_in[5];
    const float* bQ      = (const float*)d_in[6];
    const float* WK      = (const float*)d_in[7];
    const float* bK      = (const float*)d_in[8];
    const float* att     = (const float*)d_in[9];
    const float* W2      = (const float*)d_in[10];
    const float* b2      = (const float*)d_in[11];
    float* out = (float*)d_out;

    cudaFuncSetAttribute(k_hatt, cudaFuncAttributeMaxDynamicSharedMemorySize, HT_SMEM);
    cudaFuncSetAttribute(k_qk, cudaFuncAttributeMaxDynamicSharedMemorySize, QK_SMEM);
    cudaFuncSetAttribute(k_attn, cudaFuncAttributeMaxDynamicSharedMemorySize, AT_SMEM);

    k_fc1<<<dim3(64, 3), 256>>>(x, W1, b1);
    k_hatt<<<dim3(32, 4), 128, HT_SMEM>>>(adj_att);
    k_qk<<<dim3(64, 2), 256, QK_SMEM>>>(WQ, bQ, WK, bK);
    k_attn<<<dim3(32, 8, 2), 128, AT_SMEM>>>(adjs);
    k_final<<<512, 256>>>(att, W2, b2, out);
}